// round 9
// baseline (speedup 1.0000x reference)
#include <cuda_runtime.h>
#include <cuda_bf16.h>
#include <math.h>

// Problem constants
#define NN 64    // batch n
#define CC 256   // channels c
#define SS 64    // seq s
#define PP 16    // parts p
#define KK 4     // clusters k
#define NB (NN*PP)   // 1024 attention batches
#define NR (NB*SS)   // 65536 total rows

// Scratch (no cudaMalloc allowed)
__device__ float g_xt[NR*CC];           // (n,p,s,c) fp32
__device__ float g_xattn[NR*CC];        // attention out + residual
__device__ float g_protn[PP*KK*CC];
__device__ float g_clustered[PP*NN*KK*CC];
__device__ unsigned char g_idx[PP*NN*SS];
// packed bf16 hi/lo weights: [hi/lo][wsel(q,k,v,o)][128 kpair rows][256 cols]
__device__ unsigned g_pw[2*4*128*256];
// packed X planes (pairs along c): [row][128 u32]
__device__ unsigned g_xph[NR*128];
__device__ unsigned g_xpl[NR*128];
// packed Q/K planes, V fp32, H planes
__device__ unsigned g_qh[NR*128];
__device__ unsigned g_ql[NR*128];
__device__ unsigned g_kh[NR*128];
__device__ unsigned g_kl[NR*128];
__device__ float    g_v [NR*CC];
__device__ unsigned g_hh[NR*128];
__device__ unsigned g_hl[NR*128];

// ---------------------------------------------------------------------------
// bf16 split helpers
// ---------------------------------------------------------------------------
__device__ __forceinline__ void split2(float v0, float v1, unsigned& hi, unsigned& lo) {
    __nv_bfloat16 h0 = __float2bfloat16(v0);
    __nv_bfloat16 h1 = __float2bfloat16(v1);
    float l0f = v0 - __bfloat162float(h0);
    float l1f = v1 - __bfloat162float(h1);
    __nv_bfloat16 l0 = __float2bfloat16(l0f);
    __nv_bfloat16 l1 = __float2bfloat16(l1f);
    hi = (unsigned)__bfloat16_as_ushort(h0) | ((unsigned)__bfloat16_as_ushort(h1) << 16);
    lo = (unsigned)__bfloat16_as_ushort(l0) | ((unsigned)__bfloat16_as_ushort(l1) << 16);
}

__device__ __forceinline__ void mma_bf16(float c[4], const unsigned a[4], unsigned b0, unsigned b1) {
    asm volatile(
        "mma.sync.aligned.m16n8k16.row.col.f32.bf16.bf16.f32 "
        "{%0,%1,%2,%3},{%4,%5,%6,%7},{%8,%9},{%0,%1,%2,%3};"
        : "+f"(c[0]), "+f"(c[1]), "+f"(c[2]), "+f"(c[3])
        : "r"(a[0]), "r"(a[1]), "r"(a[2]), "r"(a[3]), "r"(b0), "r"(b1));
}

// ---------------------------------------------------------------------------
// Kernel P: pack weights -> hi/lo bf16 pair arrays (pairs along k)
// ---------------------------------------------------------------------------
__global__ void packw_kernel(const float* __restrict__ Wq, const float* __restrict__ Wk,
                             const float* __restrict__ Wv, const float* __restrict__ Wo) {
    int n = threadIdx.x;
    int k2 = blockIdx.x;
    int ws = blockIdx.y;
    const float* W = (ws == 0) ? Wq : (ws == 1) ? Wk : (ws == 2) ? Wv : Wo;
    float v0 = W[(2*k2)*256 + n];
    float v1 = W[(2*k2 + 1)*256 + n];
    unsigned hi, lo;
    split2(v0, v1, hi, lo);
    g_pw[ws*32768 + k2*256 + n] = hi;
    g_pw[4*32768 + ws*32768 + k2*256 + n] = lo;
}

// ---------------------------------------------------------------------------
// Kernel 0: transpose x (n,c,s,p) -> g_xt (n,p,s,c)
// ---------------------------------------------------------------------------
__global__ void transpose_kernel(const float* __restrict__ x) {
    __shared__ float tile[256*17];
    int bx = blockIdx.x;
    int n = bx >> 6, s = bx & 63;
    int t = threadIdx.x;
    const float* src = x + (size_t)n*262144 + (size_t)s*16;
    #pragma unroll
    for (int w = 0; w < 16; w++) {
        int i = t + w*256;
        int c = i >> 4, pp = i & 15;
        tile[c*17 + pp] = src[(size_t)c*1024 + pp];
    }
    __syncthreads();
    float* dst = g_xt + (size_t)n*262144 + (size_t)s*256;
    #pragma unroll
    for (int w = 0; w < 16; w++) {
        dst[(size_t)w*16384 + t] = tile[t*17 + w];
    }
}

// ---------------------------------------------------------------------------
// Kernel 0b: pack X into bf16 hi/lo pair planes
// ---------------------------------------------------------------------------
__global__ void packx_kernel() {
    int idx = blockIdx.x*256 + threadIdx.x;   // over NR*128 pairs
    float2 v = ((const float2*)g_xt)[idx];
    unsigned hi, lo;
    split2(v.x, v.y, hi, lo);
    g_xph[idx] = hi;
    g_xpl[idx] = lo;
}

// ---------------------------------------------------------------------------
// Kernel 1: normalize prototypes
// ---------------------------------------------------------------------------
__global__ void protonorm_kernel(const float* __restrict__ prot) {
    int r = blockIdx.x;
    int t = threadIdx.x;
    float v = prot[r*256 + t];
    float sq = v * v;
    #pragma unroll
    for (int off = 16; off > 0; off >>= 1)
        sq += __shfl_down_sync(0xffffffffu, sq, off);
    __shared__ float red[8];
    if ((t & 31) == 0) red[t >> 5] = sq;
    __syncthreads();
    __shared__ float rn;
    if (t == 0) {
        float sum = 0.f;
        #pragma unroll
        for (int i = 0; i < 8; i++) sum += red[i];
        rn = rsqrtf(sum);
    }
    __syncthreads();
    g_protn[r*256 + t] = v * rn;
}

// ---------------------------------------------------------------------------
// Kernel 2: instance-norm + dot + argmax -> hard idx (one block per (p,n))
// ---------------------------------------------------------------------------
__global__ __launch_bounds__(256) void assign_kernel() {
    int p = blockIdx.x, n = blockIdx.y;
    extern __shared__ float sm[];
    float* Xs = sm;              // 16384 floats
    float* P  = Xs + 16384;      // 1024
    float* MU = P + 1024;        // 256
    float* RS = MU + 256;        // 256
    int t = threadIdx.x;
    const float* src = g_xt + (size_t)(n*16 + p) * 16384;
    for (int i = t; i < 16384; i += 256) Xs[i] = src[i];
    const float* psrc = g_protn + p*1024;
    for (int i = t; i < 1024; i += 256) P[i] = psrc[i];
    __syncthreads();

    {
        float s1 = 0.f, s2 = 0.f;
        #pragma unroll
        for (int s = 0; s < 64; s++) {
            float v = Xs[s*256 + t];
            s1 += v; s2 += v*v;
        }
        float mu = s1 * 0.015625f;
        float var = s2 * 0.015625f - mu*mu;
        MU[t] = mu;
        RS[t] = rsqrtf(var + 1e-5f);
    }
    __syncthreads();

    int w = t >> 5, lane = t & 31;
    #pragma unroll
    for (int it = 0; it < 8; it++) {
        int s = w*8 + it;
        float d0 = 0.f, d1 = 0.f, d2 = 0.f, d3 = 0.f;
        #pragma unroll
        for (int cc = 0; cc < 8; cc++) {
            int c = lane + 32*cc;
            float y = (Xs[s*256 + c] - MU[c]) * RS[c];
            d0 = fmaf(y, P[c],       d0);
            d1 = fmaf(y, P[256 + c], d1);
            d2 = fmaf(y, P[512 + c], d2);
            d3 = fmaf(y, P[768 + c], d3);
        }
        #pragma unroll
        for (int off = 16; off > 0; off >>= 1) {
            d0 += __shfl_down_sync(0xffffffffu, d0, off);
            d1 += __shfl_down_sync(0xffffffffu, d1, off);
            d2 += __shfl_down_sync(0xffffffffu, d2, off);
            d3 += __shfl_down_sync(0xffffffffu, d3, off);
        }
        if (lane == 0) {
            int best = 0; float bv = d0;
            if (d1 > bv) { bv = d1; best = 1; }
            if (d2 > bv) { bv = d2; best = 2; }
            if (d3 > bv) { bv = d3; best = 3; }
            g_idx[(p*64 + n)*64 + s] = (unsigned char)best;
        }
    }
}

// ---------------------------------------------------------------------------
// Kernel 3: mode over parts -> cluster_indices (as float)
// ---------------------------------------------------------------------------
__global__ void mode_kernel(float* __restrict__ outci) {
    int id = blockIdx.x*256 + threadIdx.x;
    if (id >= NN*SS) return;
    int n = id >> 6, s = id & 63;
    int c0 = 0, c1 = 0, c2 = 0, c3 = 0;
    #pragma unroll
    for (int p = 0; p < 16; p++) {
        int a = g_idx[(p*64 + n)*64 + s];
        c0 += (a == 0); c1 += (a == 1); c2 += (a == 2); c3 += (a == 3);
    }
    int best = 0, bc = c0;
    if (c1 > bc) { bc = c1; best = 1; }
    if (c2 > bc) { bc = c2; best = 2; }
    if (c3 > bc) { bc = c3; best = 3; }
    outci[id] = (float)best;
}

// ---------------------------------------------------------------------------
// Kernel 4a: QKV projection GEMM [65536 x 256] x [256 x 768]
// grid 512 (M-groups of 128 rows), 512 threads.
// smem: xhi/xlo [128][132], whi/wlo [128][72]  = 208896 B
// Loops nt = 0..11 (Q0..3, K0..3, V0..3 column tiles of 64), weight tile
// staged in smem per nt.  X read ONCE per 128 rows.
// ---------------------------------------------------------------------------
#define QX_XH 0
#define QX_XL 16896
#define QX_WH 33792
#define QX_WL 43008
#define QX_U32 52224

__global__ __launch_bounds__(512, 1) void qkv_kernel(
    const float* __restrict__ bq, const float* __restrict__ bk,
    const float* __restrict__ bv) {
    extern __shared__ unsigned smem[];
    int t = threadIdx.x;
    int w = t >> 5, lane = t & 31;
    int g = lane >> 2, tg = lane & 3;
    int row0 = blockIdx.x * 128;

    // fill X planes (uint4, coalesced)
    {
        const uint4* sh = (const uint4*)(g_xph + (size_t)row0*128);
        const uint4* sl = (const uint4*)(g_xpl + (size_t)row0*128);
        for (int idx = t; idx < 4096; idx += 512) {
            int r = idx >> 5, c4 = idx & 31;
            *(uint4*)(smem + QX_XH + r*132 + 4*c4) = sh[idx];
            *(uint4*)(smem + QX_XL + r*132 + 4*c4) = sl[idx];
        }
    }

    int mt = w >> 1, half = w & 1;
    int rowA = mt*16 + g;

    for (int nt = 0; nt < 12; nt++) {
        int sel = nt >> 2;
        int c0mat = (nt & 3) * 64;
        __syncthreads();   // X ready / prev-W consumers done
        // fill W tile
        {
            const unsigned* wsrc = g_pw + sel*32768 + c0mat;
            for (int idx = t; idx < 8192; idx += 512) {
                int kp = idx >> 6, col = idx & 63;
                smem[QX_WH + kp*72 + col] = wsrc[kp*256 + col];
                smem[QX_WL + kp*72 + col] = wsrc[131072 + kp*256 + col];
            }
        }
        __syncthreads();

        float acc[4][4];
        #pragma unroll
        for (int i = 0; i < 4; i++)
            #pragma unroll
            for (int j = 0; j < 4; j++) acc[i][j] = 0.f;

        for (int kt = 0; kt < 16; kt++) {
            unsigned ah[4], al[4];
            int base = rowA*132 + 8*kt + tg;
            ah[0] = smem[QX_XH + base];
            ah[1] = smem[QX_XH + base + 8*132];
            ah[2] = smem[QX_XH + base + 4];
            ah[3] = smem[QX_XH + base + 8*132 + 4];
            al[0] = smem[QX_XL + base];
            al[1] = smem[QX_XL + base + 8*132];
            al[2] = smem[QX_XL + base + 4];
            al[3] = smem[QX_XL + base + 8*132 + 4];
            int w0 = (8*kt + tg)*72;
            int w1 = (8*kt + 4 + tg)*72;
            #pragma unroll
            for (int nf = 0; nf < 4; nf++) {
                int col = half*32 + nf*8 + g;
                unsigned bh0 = smem[QX_WH + w0 + col], bh1 = smem[QX_WH + w1 + col];
                unsigned bl0 = smem[QX_WL + w0 + col], bl1 = smem[QX_WL + w1 + col];
                mma_bf16(acc[nf], ah, bh0, bh1);
                mma_bf16(acc[nf], ah, bl0, bl1);
                mma_bf16(acc[nf], al, bh0, bh1);
            }
        }

        // epilogue
        const float* bias = (sel == 0) ? bq : (sel == 1) ? bk : bv;
        int rg0 = row0 + rowA, rg1 = row0 + rowA + 8;
        #pragma unroll
        for (int nf = 0; nf < 4; nf++) {
            int col = c0mat + half*32 + nf*8 + 2*tg;   // col within matrix (0..255)
            float bz0 = bias[col], bz1 = bias[col + 1];
            float c0 = acc[nf][0] + bz0, c1 = acc[nf][1] + bz1;
            float c2 = acc[nf][2] + bz0, c3 = acc[nf][3] + bz1;
            if (sel == 0) {
                unsigned hi, lo;
                split2(c0, c1, hi, lo);
                g_qh[(size_t)rg0*128 + (col >> 1)] = hi;
                g_ql[(size_t)rg0*128 + (col >> 1)] = lo;
                split2(c2, c3, hi, lo);
                g_qh[(size_t)rg1*128 + (col >> 1)] = hi;
                g_ql[(size_t)rg1*128 + (col >> 1)] = lo;
            } else if (sel == 1) {
                unsigned hi, lo;
                split2(c0, c1, hi, lo);
                g_kh[(size_t)rg0*128 + (col >> 1)] = hi;
                g_kl[(size_t)rg0*128 + (col >> 1)] = lo;
                split2(c2, c3, hi, lo);
                g_kh[(size_t)rg1*128 + (col >> 1)] = hi;
                g_kl[(size_t)rg1*128 + (col >> 1)] = lo;
            } else {
                *(float2*)(g_v + (size_t)rg0*256 + col) = make_float2(c0, c1);
                *(float2*)(g_v + (size_t)rg1*256 + col) = make_float2(c2, c3);
            }
        }
    }
}

// ---------------------------------------------------------------------------
// Kernel 4b: attention core per (batch, head): scores, softmax, S@V
// 128 threads, 2 CTAs/SM. smem u32 offsets (stride-36 planes):
// ---------------------------------------------------------------------------
#define CO_QH 0          // Q hi (later S hi)
#define CO_QL 2304
#define CO_KH 4608
#define CO_KL 6912
#define CO_VH 9216       // V^T packed (pairs along s)
#define CO_VL 11520
#define CO_SF 13824      // scores fp32 [64][66]
#define CO_VF 18048      // V fp32 staging [64][66]
#define CO_U32 22272     // 89088 B

__global__ __launch_bounds__(128, 2) void core_kernel() {
    extern __shared__ unsigned smem[];
    float* Sf = (float*)(smem + CO_SF);
    float* Vf = (float*)(smem + CO_VF);
    int t = threadIdx.x;
    int w = t >> 5, lane = t & 31;
    int g = lane >> 2, tg = lane & 3;
    int b = blockIdx.x, h = blockIdx.y;
    size_t rbase = (size_t)b * 64;

    // fill Q/K planes + V fp32
    for (int idx = t; idx < 2048; idx += 128) {
        int s = idx >> 5, jj = idx & 31;
        size_t go = (rbase + s)*128 + h*32 + jj;
        smem[CO_QH + s*36 + jj] = g_qh[go];
        smem[CO_QL + s*36 + jj] = g_ql[go];
        smem[CO_KH + s*36 + jj] = g_kh[go];
        smem[CO_KL + s*36 + jj] = g_kl[go];
    }
    for (int idx = t; idx < 4096; idx += 128) {
        int s = idx >> 6, d = idx & 63;
        Vf[s*66 + d] = g_v[(rbase + s)*256 + h*64 + d];
    }
    __syncthreads();

    int rowA = w*16 + g;   // warp w handles rows w*16 .. w*16+15

    // pack V transposed (pairs along s)
    for (int idx = t; idx < 2048; idx += 128) {
        int dim = idx >> 5, sh = idx & 31;
        unsigned hi, lo;
        split2(Vf[(2*sh)*66 + dim], Vf[(2*sh + 1)*66 + dim], hi, lo);
        smem[CO_VH + dim*36 + sh] = hi;
        smem[CO_VL + dim*36 + sh] = lo;
    }
    // scores S = Q K^T * 0.125
    {
        float sacc[8][4];
        #pragma unroll
        for (int i = 0; i < 8; i++)
            #pragma unroll
            for (int j = 0; j < 4; j++) sacc[i][j] = 0.f;
        #pragma unroll
        for (int kt = 0; kt < 4; kt++) {
            unsigned ah[4], al[4];
            int base = rowA*36 + 8*kt + tg;
            ah[0] = smem[CO_QH + base];     ah[1] = smem[CO_QH + base + 8*36];
            ah[2] = smem[CO_QH + base + 4]; ah[3] = smem[CO_QH + base + 8*36 + 4];
            al[0] = smem[CO_QL + base];     al[1] = smem[CO_QL + base + 8*36];
            al[2] = smem[CO_QL + base + 4]; al[3] = smem[CO_QL + base + 8*36 + 4];
            #pragma unroll
            for (int nf = 0; nf < 8; nf++) {
                int key = nf*8 + g;
                int bb = key*36 + 8*kt + tg;
                unsigned bh0 = smem[CO_KH + bb], bh1 = smem[CO_KH + bb + 4];
                unsigned bl0 = smem[CO_KL + bb], bl1 = smem[CO_KL + bb + 4];
                mma_bf16(sacc[nf], ah, bh0, bh1);
                mma_bf16(sacc[nf], ah, bl0, bl1);
                mma_bf16(sacc[nf], al, bh0, bh1);
            }
        }
        #pragma unroll
        for (int nf = 0; nf < 8; nf++) {
            int col = nf*8 + 2*tg;
            *(float2*)(Sf + rowA*66 + col) =
                make_float2(sacc[nf][0]*0.125f, sacc[nf][1]*0.125f);
            *(float2*)(Sf + (rowA + 8)*66 + col) =
                make_float2(sacc[nf][2]*0.125f, sacc[nf][3]*0.125f);
        }
    }
    __syncthreads();

    // causal softmax, 2 threads per row
    {
        int row = t >> 1, sub = t & 1;
        float* Srow = Sf + row*66;
        float m = -3.402823466e38f;
        for (int j = sub; j <= row; j += 2) m = fmaxf(m, Srow[j]);
        m = fmaxf(m, __shfl_xor_sync(0xffffffffu, m, 1));
        float ssum = 0.f;
        for (int j = sub; j < 64; j += 2) {
            if (j <= row) {
                float e = __expf(Srow[j] - m);
                Srow[j] = e; ssum += e;
            } else Srow[j] = 0.f;
        }
        ssum += __shfl_xor_sync(0xffffffffu, ssum, 1);
        float inv = 1.f / ssum;
        for (int j = sub; j <= row; j += 2) Srow[j] *= inv;
    }
    __syncthreads();

    // pack probs into Q planes (Q dead)
    for (int idx = t; idx < 2048; idx += 128) {
        int r = idx >> 5, jh = idx & 31;
        unsigned hi, lo;
        split2(Sf[r*66 + 2*jh], Sf[r*66 + 2*jh + 1], hi, lo);
        smem[CO_QH + r*36 + jh] = hi;
        smem[CO_QL + r*36 + jh] = lo;
    }
    __syncthreads();

    // H = S @ V -> packed global H planes
    {
        float hacc[8][4];
        #pragma unroll
        for (int i = 0; i < 8; i++)
            #pragma unroll
            for (int j = 0; j < 4; j++) hacc[i][j] = 0.f;
        #pragma unroll
        for (int kt = 0; kt < 4; kt++) {
            unsigned ah[4], al[4];
            int base = rowA*36 + 8*kt + tg;
            ah[0] = smem[CO_QH + base];     ah[1] = smem[CO_QH + base + 8*36];
            ah[2] = smem[CO_QH + base + 4]; ah[3] = smem[CO_QH + base + 8*36 + 4];
            al[0] = smem[CO_QL + base];     al[1] = smem[CO_QL + base + 8*36];
            al[2] = smem[CO_QL + base + 4]; al[3] = smem[CO_QL + base + 8*36 + 4];
            #pragma unroll
            for (int nf = 0; nf < 8; nf++) {
                int dim = nf*8 + g;
                int bb = dim*36 + 8*kt + tg;
                unsigned bh0 = smem[CO_VH + bb], bh1 = smem[CO_VH + bb + 4];
                unsigned bl0 = smem[CO_VL + bb], bl1 = smem[CO_VL + bb + 4];
                mma_bf16(hacc[nf], ah, bh0, bh1);
                mma_bf16(hacc[nf], ah, bl0, bl1);
                mma_bf16(hacc[nf], al, bh0, bh1);
            }
        }
        #pragma unroll
        for (int nf = 0; nf < 8; nf++) {
            int gcol = h*64 + nf*8 + 2*tg;    // global concat col
            unsigned hi, lo;
            split2(hacc[nf][0], hacc[nf][1], hi, lo);
            g_hh[(rbase + rowA)*128 + (gcol >> 1)] = hi;
            g_hl[(rbase + rowA)*128 + (gcol >> 1)] = lo;
            split2(hacc[nf][2], hacc[nf][3], hi, lo);
            g_hh[(rbase + rowA + 8)*128 + (gcol >> 1)] = hi;
            g_hl[(rbase + rowA + 8)*128 + (gcol >> 1)] = lo;
        }
    }
}

// ---------------------------------------------------------------------------
// Kernel 4c: output projection GEMM [65536 x 256] x Wo[256 x 256] + bo + X
// same structure as qkv_kernel; 4 N-tiles.
// ---------------------------------------------------------------------------
__global__ __launch_bounds__(512, 1) void kout_kernel(const float* __restrict__ bo) {
    extern __shared__ unsigned smem[];
    int t = threadIdx.x;
    int w = t >> 5, lane = t & 31;
    int g = lane >> 2, tg = lane & 3;
    int row0 = blockIdx.x * 128;

    {
        const uint4* sh = (const uint4*)(g_hh + (size_t)row0*128);
        const uint4* sl = (const uint4*)(g_hl + (size_t)row0*128);
        for (int idx = t; idx < 4096; idx += 512) {
            int r = idx >> 5, c4 = idx & 31;
            *(uint4*)(smem + QX_XH + r*132 + 4*c4) = sh[idx];
            *(uint4*)(smem + QX_XL + r*132 + 4*c4) = sl[idx];
        }
    }

    int mt = w >> 1, half = w & 1;
    int rowA = mt*16 + g;

    for (int nt = 0; nt < 4; nt++) {
        __syncthreads();
        {
            const unsigned* wsrc = g_pw + 3*32768 + nt*64;
            for (int idx = t; idx < 8192; idx += 512) {
                int kp = idx >> 6, col = idx & 63;
                smem[QX_WH + kp*72 + col] = wsrc[kp*256 + col];
                smem[QX_WL + kp*72 + col] = wsrc[131072 + kp*256 + col];
            }
        }
        __syncthreads();

        float acc[4][4];
        #pragma unroll
        for (int i = 0; i < 4; i++)
            #pragma unroll
            for (int j = 0; j < 4; j++) acc[i][j] = 0.f;

        for (int kt = 0; kt < 16; kt++) {
            unsigned ah[4], al[4];
            int base = rowA*132 + 8*kt + tg;
            ah[0] = smem[QX_XH + base];
            ah[1] = smem[QX_XH + base + 8*132];
            ah[2] = smem[QX_XH + base + 4];
            ah[3] = smem[QX_XH + base + 8*132 + 4];
            al[0] = smem[QX_XL + base];
            al[1] = smem[QX_XL + base + 8*132];
            al[2] = smem[QX_XL + base + 4];
            al[3] = smem[QX_XL + base + 8*132 + 4];
            int w0 = (8*kt + tg)*72;
            int w1 = (8*kt + 4 + tg)*72;
            #pragma unroll
            for (int nf = 0; nf < 4; nf++) {
                int col = half*32 + nf*8 + g;
                unsigned bh0 = smem[QX_WH + w0 + col], bh1 = smem[QX_WH + w1 + col];
                unsigned bl0 = smem[QX_WL + w0 + col], bl1 = smem[QX_WL + w1 + col];
                mma_bf16(acc[nf], ah, bh0, bh1);
                mma_bf16(acc[nf], ah, bl0, bl1);
                mma_bf16(acc[nf], al, bh0, bh1);
            }
        }

        int rg0 = row0 + rowA, rg1 = row0 + rowA + 8;
        #pragma unroll
        for (int nf = 0; nf < 4; nf++) {
            int col = nt*64 + half*32 + nf*8 + 2*tg;
            float bz0 = bo[col], bz1 = bo[col + 1];
            float2 x0 = *(const float2*)(g_xt + (size_t)rg0*256 + col);
            float2 x1 = *(const float2*)(g_xt + (size_t)rg1*256 + col);
            *(float2*)(g_xattn + (size_t)rg0*256 + col) =
                make_float2(acc[nf][0] + bz0 + x0.x, acc[nf][1] + bz1 + x0.y);
            *(float2*)(g_xattn + (size_t)rg1*256 + col) =
                make_float2(acc[nf][2] + bz0 + x1.x, acc[nf][3] + bz1 + x1.y);
        }
    }
}

// ---------------------------------------------------------------------------
// Kernel 5: scatter-max pooling
// ---------------------------------------------------------------------------
__global__ __launch_bounds__(256) void scatter_kernel() {
    int p = blockIdx.x, n = blockIdx.y, t = threadIdx.x;
    __shared__ unsigned char ids[64];
    if (t < 64) ids[t] = g_idx[(p*64 + n)*64 + t];
    __syncthreads();
    int c0 = 0, c1 = 0, c2 = 0, c3 = 0;
    #pragma unroll 8
    for (int s = 0; s < 64; s++) {
        int a = ids[s];
        c0 += (a == 0); c1 += (a == 1); c2 += (a == 2); c3 += (a == 3);
    }
    const float* src = g_xattn + (size_t)(n*16 + p)*16384 + t;
    float m0 = -3.402823466e38f, m1 = m0, m2 = m0, m3 = m0;
    #pragma unroll 8
    for (int s = 0; s < 64; s++) {
        float v = src[s*256];
        int a = ids[s];
        if (a == 0) m0 = fmaxf(m0, v);
        else if (a == 1) m1 = fmaxf(m1, v);
        else if (a == 2) m2 = fmaxf(m2, v);
        else m3 = fmaxf(m3, v);
    }
    if (c0 < 64) m0 = fmaxf(m0, 0.f);
    if (c1 < 64) m1 = fmaxf(m1, 0.f);
    if (c2 < 64) m2 = fmaxf(m2, 0.f);
    if (c3 < 64) m3 = fmaxf(m3, 0.f);
    float* dst = g_clustered + (size_t)(p*64 + n)*1024 + t;
    dst[0]   = m0;
    dst[256] = m1;
    dst[512] = m2;
    dst[768] = m3;
}

// ---------------------------------------------------------------------------
// Kernel 6: per-part FC
// ---------------------------------------------------------------------------
__global__ __launch_bounds__(256) void fc_kernel(const float* __restrict__ fcb,
                                                 float* __restrict__ out) {
    int p = blockIdx.x, n0 = blockIdx.y * 16, t = threadIdx.x;
    extern __shared__ float cl[];
    for (int nn = 0; nn < 16; nn++) {
        const float* src = g_clustered + (size_t)(p*64 + n0 + nn)*1024;
        for (int i = t; i < 1024; i += 256) cl[nn*1024 + i] = src[i];
    }
    __syncthreads();
    int o0 = t & 63, g = t >> 6;
    float acc[4][4];
    #pragma unroll
    for (int a = 0; a < 4; a++)
        #pragma unroll
        for (int bb = 0; bb < 4; bb++) acc[a][bb] = 0.f;
    const float* F = fcb + (size_t)p*1024*256 + o0;
    for (int kc = 0; kc < 1024; kc++) {
        float wv[4], cv[4];
        #pragma unroll
        for (int bb = 0; bb < 4; bb++) wv[bb] = F[(size_t)kc*256 + 64*bb];
        #pragma unroll
        for (int a = 0; a < 4; a++) cv[a] = cl[(g*4 + a)*1024 + kc];
        #pragma unroll
        for (int a = 0; a < 4; a++)
            #pragma unroll
            for (int bb = 0; bb < 4; bb++)
                acc[a][bb] = fmaf(cv[a], wv[bb], acc[a][bb]);
    }
    #pragma unroll
    for (int a = 0; a < 4; a++) {
        int n = n0 + g*4 + a;
        #pragma unroll
        for (int bb = 0; bb < 4; bb++) {
            int o = o0 + 64*bb;
            out[(size_t)n*4096 + o*16 + p] = acc[a][bb];
        }
    }
}

// ---------------------------------------------------------------------------
extern "C" void kernel_launch(void* const* d_in, const int* in_sizes, int n_in,
                              void* d_out, int out_size) {
    const float* x    = (const float*)d_in[0];
    const float* prot = (const float*)d_in[1];
    const float* Wq   = (const float*)d_in[2];
    const float* bq   = (const float*)d_in[3];
    const float* Wk   = (const float*)d_in[4];
    const float* bk   = (const float*)d_in[5];
    const float* Wv   = (const float*)d_in[6];
    const float* bv   = (const float*)d_in[7];
    const float* Wo   = (const float*)d_in[8];
    const float* bo   = (const float*)d_in[9];
    const float* fcb  = (const float*)d_in[10];
    float* out = (float*)d_out;

    cudaFuncSetAttribute(qkv_kernel,  cudaFuncAttributeMaxDynamicSharedMemorySize, QX_U32*4);
    cudaFuncSetAttribute(kout_kernel, cudaFuncAttributeMaxDynamicSharedMemorySize, QX_U32*4);
    cudaFuncSetAttribute(core_kernel, cudaFuncAttributeMaxDynamicSharedMemorySize, CO_U32*4);
    cudaFuncSetAttribute(assign_kernel, cudaFuncAttributeMaxDynamicSharedMemorySize, 71680);
    cudaFuncSetAttribute(fc_kernel, cudaFuncAttributeMaxDynamicSharedMemorySize, 65536);

    packw_kernel<<<dim3(128, 4), 256>>>(Wq, Wk, Wv, Wo);
    transpose_kernel<<<NN*SS, 256>>>(x);
    packx_kernel<<<NR*128/256, 256>>>();
    protonorm_kernel<<<PP*KK, 256>>>(prot);
    assign_kernel<<<dim3(PP, NN), 256, 71680>>>();
    if (out_size >= NN*CC*PP + NN*SS)
        mode_kernel<<<16, 256>>>(out + NN*CC*PP);
    qkv_kernel<<<512, 512, QX_U32*4>>>(bq, bk, bv);
    core_kernel<<<dim3(NB, 4), 128, CO_U32*4>>>();
    kout_kernel<<<512, 512, QX_U32*4>>>(bo);
    scatter_kernel<<<dim3(PP, NN), 256>>>();
    fc_kernel<<<dim3(PP, 4), 256, 65536>>>(fcb, out);
}

// round 11
// speedup vs baseline: 1.1952x; 1.1952x over previous
#include <cuda_runtime.h>
#include <cuda_bf16.h>
#include <math.h>

// Problem constants
#define NN 64
#define CC 256
#define SS 64
#define PP 16
#define KK 4
#define NB (NN*PP)   // 1024 attention batches
#define NR (NB*SS)   // 65536 rows

// Scratch (no cudaMalloc allowed)
__device__ float g_xt[NR*CC];           // (n,p,s,c) fp32
__device__ float g_xattn[NR*CC];        // attention out + residual
__device__ float g_protn[PP*KK*CC];
__device__ float g_clustered[PP*NN*KK*CC];
__device__ unsigned char g_idx[PP*NN*SS];
// tf32 planes (u32 bit patterns)
__device__ unsigned g_xq[NR*CC];        // X tf32
__device__ unsigned g_q [NR*CC];        // Q tf32
__device__ unsigned g_k [NR*CC];        // K tf32
__device__ unsigned g_vq[NR*CC];        // V tf32
__device__ unsigned g_h [NR*CC];        // head-concat out tf32
// tf32 weights [ws][k][n], ws = q,k,v,o
__device__ unsigned g_wt[4*256*256];

// ---------------------------------------------------------------------------
// helpers
// ---------------------------------------------------------------------------
__device__ __forceinline__ unsigned f2tf(float f) {
    unsigned u;
    asm("cvt.rna.tf32.f32 %0, %1;" : "=r"(u) : "f"(f));
    return u;
}

__device__ __forceinline__ void mma_tf32(float c[4], const unsigned a[4],
                                         unsigned b0, unsigned b1) {
    asm volatile(
        "mma.sync.aligned.m16n8k8.row.col.f32.tf32.tf32.f32 "
        "{%0,%1,%2,%3},{%4,%5,%6,%7},{%8,%9},{%0,%1,%2,%3};"
        : "+f"(c[0]), "+f"(c[1]), "+f"(c[2]), "+f"(c[3])
        : "r"(a[0]), "r"(a[1]), "r"(a[2]), "r"(a[3]), "r"(b0), "r"(b1));
}

// ---------------------------------------------------------------------------
// Kernel P1: weights -> tf32
// ---------------------------------------------------------------------------
__global__ void packw_kernel(const float* __restrict__ Wq, const float* __restrict__ Wk,
                             const float* __restrict__ Wv, const float* __restrict__ Wo) {
    int ws = blockIdx.y;
    int i = blockIdx.x*256 + threadIdx.x;   // 0..65535
    const float* W = (ws == 0) ? Wq : (ws == 1) ? Wk : (ws == 2) ? Wv : Wo;
    g_wt[ws*65536 + i] = f2tf(W[i]);
}

// ---------------------------------------------------------------------------
// Kernel 0: transpose x (n,c,s,p) -> g_xt (n,p,s,c)
// ---------------------------------------------------------------------------
__global__ void transpose_kernel(const float* __restrict__ x) {
    __shared__ float tile[256*17];
    int bx = blockIdx.x;
    int n = bx >> 6, s = bx & 63;
    int t = threadIdx.x;
    const float* src = x + (size_t)n*262144 + (size_t)s*16;
    #pragma unroll
    for (int w = 0; w < 16; w++) {
        int i = t + w*256;
        int c = i >> 4, pp = i & 15;
        tile[c*17 + pp] = src[(size_t)c*1024 + pp];
    }
    __syncthreads();
    float* dst = g_xt + (size_t)n*262144 + (size_t)s*256;
    #pragma unroll
    for (int w = 0; w < 16; w++) {
        dst[(size_t)w*16384 + t] = tile[t*17 + w];
    }
}

// ---------------------------------------------------------------------------
// Kernel P2: X -> tf32 planes
// ---------------------------------------------------------------------------
__global__ void packx_kernel() {
    int idx = blockIdx.x*256 + threadIdx.x;   // over NR*64 float4
    float4 v = ((const float4*)g_xt)[idx];
    uint4 o;
    o.x = f2tf(v.x); o.y = f2tf(v.y); o.z = f2tf(v.z); o.w = f2tf(v.w);
    ((uint4*)g_xq)[idx] = o;
}

// ---------------------------------------------------------------------------
// qkv: [65536 x 256] x [256 x 768] tf32; 512 CTAs x 512 thr
// smem u32: Xs 128 rows stride 260 (33280) + Ws 256 k stride 72 (18432)
// ---------------------------------------------------------------------------
#define QK_WS 33280
#define QK_U32 51712    // 206848 B

__global__ __launch_bounds__(512, 1) void qkv_kernel(
    const float* __restrict__ bq, const float* __restrict__ bk,
    const float* __restrict__ bv) {
    extern __shared__ unsigned sm[];
    unsigned* Xs = sm;
    unsigned* Ws = sm + QK_WS;
    int t = threadIdx.x;
    int w = t >> 5, lane = t & 31;
    int g = lane >> 2, tg = lane & 3;
    int row0 = blockIdx.x * 128;

    {
        const uint4* xs = (const uint4*)(g_xq + (size_t)row0*256);
        for (int idx = t; idx < 8192; idx += 512) {
            int r = idx >> 6, c4 = idx & 63;
            *(uint4*)(Xs + r*260 + 4*c4) = xs[idx];
        }
    }

    int mt = w >> 1, half = w & 1;
    int rowA = mt*16 + g;

    for (int nt = 0; nt < 12; nt++) {
        int sel = nt >> 2, nto = nt & 3;
        __syncthreads();
        {
            const unsigned* wsrc = g_wt + sel*65536 + nto*64;
            for (int idx = t; idx < 4096; idx += 512) {
                int k = idx >> 4, c4 = idx & 15;
                *(uint4*)(Ws + k*72 + 4*c4) = *(const uint4*)(wsrc + k*256 + 4*c4);
            }
        }
        __syncthreads();

        float acc[4][4];
        #pragma unroll
        for (int i = 0; i < 4; i++)
            #pragma unroll
            for (int j = 0; j < 4; j++) acc[i][j] = 0.f;

        for (int s = 0; s < 32; s++) {
            unsigned a[4];
            int ab = rowA*260 + 8*s + tg;
            a[0] = Xs[ab];
            a[1] = Xs[ab + 8*260];
            a[2] = Xs[ab + 4];
            a[3] = Xs[ab + 8*260 + 4];
            int w0 = (8*s + tg)*72, w1 = (8*s + tg + 4)*72;
            #pragma unroll
            for (int nf = 0; nf < 4; nf++) {
                int col = half*32 + nf*8 + g;
                mma_tf32(acc[nf], a, Ws[w0 + col], Ws[w1 + col]);
            }
        }

        const float* bias = (sel == 0) ? bq : (sel == 1) ? bk : bv;
        unsigned* dst = (sel == 0) ? g_q : (sel == 1) ? g_k : g_vq;
        size_t rg0 = (size_t)(row0 + rowA), rg1 = rg0 + 8;
        #pragma unroll
        for (int nf = 0; nf < 4; nf++) {
            int mcol = nto*64 + half*32 + nf*8 + 2*tg;
            float b0 = bias[mcol], b1 = bias[mcol + 1];
            uint2 o0, o1;
            o0.x = f2tf(acc[nf][0] + b0); o0.y = f2tf(acc[nf][1] + b1);
            o1.x = f2tf(acc[nf][2] + b0); o1.y = f2tf(acc[nf][3] + b1);
            *(uint2*)(dst + rg0*256 + mcol) = o0;
            *(uint2*)(dst + rg1*256 + mcol) = o1;
        }
    }
}

// ---------------------------------------------------------------------------
// core: per (batch, head) scores + softmax + S@V, tf32. 128 thr, 2 CTAs/SM
// smem u32: Qs@0 (64x76), Ks@4864, Vt@9728, Sf fp32 @14592 (64x68)
// ---------------------------------------------------------------------------
#define C_Q 0
#define C_K 4864
#define C_V 9728
#define C_S 14592
#define C_U32 18944   // 75776 B

__global__ __launch_bounds__(128, 2) void core_kernel() {
    extern __shared__ unsigned sm[];
    float* Sf = (float*)(sm + C_S);
    int t = threadIdx.x;
    int w = t >> 5, lane = t & 31;
    int g = lane >> 2, tg = lane & 3;
    int b = blockIdx.x, h = blockIdx.y;
    size_t rbase = (size_t)b * 64;

    for (int idx = t; idx < 1024; idx += 128) {
        int s = idx >> 4, c4 = idx & 15;
        *(uint4*)(sm + C_Q + s*76 + 4*c4) = *(const uint4*)(g_q + (rbase + s)*256 + h*64 + 4*c4);
        *(uint4*)(sm + C_K + s*76 + 4*c4) = *(const uint4*)(g_k + (rbase + s)*256 + h*64 + 4*c4);
    }
    for (int idx = t; idx < 4096; idx += 128) {
        int s = idx >> 6, d = idx & 63;
        sm[C_V + d*76 + s] = g_vq[(rbase + s)*256 + h*64 + d];   // transposed V
    }
    __syncthreads();

    int rowA = w*16 + g;

    // scores = Q K^T * 0.125
    {
        float sacc[8][4];
        #pragma unroll
        for (int i = 0; i < 8; i++)
            #pragma unroll
            for (int j = 0; j < 4; j++) sacc[i][j] = 0.f;
        #pragma unroll
        for (int s8 = 0; s8 < 8; s8++) {
            unsigned a[4];
            int ab = C_Q + rowA*76 + 8*s8 + tg;
            a[0] = sm[ab]; a[1] = sm[ab + 8*76]; a[2] = sm[ab + 4]; a[3] = sm[ab + 8*76 + 4];
            #pragma unroll
            for (int nf = 0; nf < 8; nf++) {
                int key = nf*8 + g;
                int bb = C_K + key*76 + 8*s8 + tg;
                mma_tf32(sacc[nf], a, sm[bb], sm[bb + 4]);
            }
        }
        #pragma unroll
        for (int nf = 0; nf < 8; nf++) {
            int col = nf*8 + 2*tg;
            *(float2*)(Sf + rowA*68 + col) =
                make_float2(sacc[nf][0]*0.125f, sacc[nf][1]*0.125f);
            *(float2*)(Sf + (rowA + 8)*68 + col) =
                make_float2(sacc[nf][2]*0.125f, sacc[nf][3]*0.125f);
        }
    }
    __syncthreads();

    // causal softmax, 2 threads per row
    {
        int row = t >> 1, sub = t & 1;
        float* Srow = Sf + row*68;
        float m = -3.402823466e38f;
        for (int j = sub; j <= row; j += 2) m = fmaxf(m, Srow[j]);
        m = fmaxf(m, __shfl_xor_sync(0xffffffffu, m, 1));
        float ssum = 0.f;
        for (int j = sub; j < 64; j += 2) {
            if (j <= row) {
                float e = __expf(Srow[j] - m);
                Srow[j] = e; ssum += e;
            } else Srow[j] = 0.f;
        }
        ssum += __shfl_xor_sync(0xffffffffu, ssum, 1);
        float inv = 1.f / ssum;
        for (int j = sub; j <= row; j += 2) Srow[j] *= inv;
    }
    __syncthreads();

    // probs -> tf32 into Qs (dead)
    for (int idx = t; idx < 4096; idx += 128) {
        int r = idx >> 6, j = idx & 63;
        sm[C_Q + r*76 + j] = f2tf(Sf[r*68 + j]);
    }
    __syncthreads();

    // H = S @ V
    {
        float hacc[8][4];
        #pragma unroll
        for (int i = 0; i < 8; i++)
            #pragma unroll
            for (int j = 0; j < 4; j++) hacc[i][j] = 0.f;
        #pragma unroll
        for (int s8 = 0; s8 < 8; s8++) {
            unsigned a[4];
            int ab = C_Q + rowA*76 + 8*s8 + tg;
            a[0] = sm[ab]; a[1] = sm[ab + 8*76]; a[2] = sm[ab + 4]; a[3] = sm[ab + 8*76 + 4];
            #pragma unroll
            for (int nf = 0; nf < 8; nf++) {
                int dim = nf*8 + g;
                int bb = C_V + dim*76 + 8*s8 + tg;
                mma_tf32(hacc[nf], a, sm[bb], sm[bb + 4]);
            }
        }
        #pragma unroll
        for (int nf = 0; nf < 8; nf++) {
            int gcol = h*64 + nf*8 + 2*tg;
            uint2 o0, o1;
            o0.x = f2tf(hacc[nf][0]); o0.y = f2tf(hacc[nf][1]);
            o1.x = f2tf(hacc[nf][2]); o1.y = f2tf(hacc[nf][3]);
            *(uint2*)(g_h + (rbase + rowA)*256 + gcol) = o0;
            *(uint2*)(g_h + (rbase + rowA + 8)*256 + gcol) = o1;
        }
    }
}

// ---------------------------------------------------------------------------
// kout: [65536 x 256] x Wo + bo + residual, tf32
// ---------------------------------------------------------------------------
__global__ __launch_bounds__(512, 1) void kout_kernel(const float* __restrict__ bo) {
    extern __shared__ unsigned sm[];
    unsigned* Xs = sm;
    unsigned* Ws = sm + QK_WS;
    int t = threadIdx.x;
    int w = t >> 5, lane = t & 31;
    int g = lane >> 2, tg = lane & 3;
    int row0 = blockIdx.x * 128;

    {
        const uint4* xs = (const uint4*)(g_h + (size_t)row0*256);
        for (int idx = t; idx < 8192; idx += 512) {
            int r = idx >> 6, c4 = idx & 63;
            *(uint4*)(Xs + r*260 + 4*c4) = xs[idx];
        }
    }

    int mt = w >> 1, half = w & 1;
    int rowA = mt*16 + g;

    for (int nt = 0; nt < 4; nt++) {
        __syncthreads();
        {
            const unsigned* wsrc = g_wt + 3*65536 + nt*64;
            for (int idx = t; idx < 4096; idx += 512) {
                int k = idx >> 4, c4 = idx & 15;
                *(uint4*)(Ws + k*72 + 4*c4) = *(const uint4*)(wsrc + k*256 + 4*c4);
            }
        }
        __syncthreads();

        float acc[4][4];
        #pragma unroll
        for (int i = 0; i < 4; i++)
            #pragma unroll
            for (int j = 0; j < 4; j++) acc[i][j] = 0.f;

        for (int s = 0; s < 32; s++) {
            unsigned a[4];
            int ab = rowA*260 + 8*s + tg;
            a[0] = Xs[ab];
            a[1] = Xs[ab + 8*260];
            a[2] = Xs[ab + 4];
            a[3] = Xs[ab + 8*260 + 4];
            int w0 = (8*s + tg)*72, w1 = (8*s + tg + 4)*72;
            #pragma unroll
            for (int nf = 0; nf < 4; nf++) {
                int col = half*32 + nf*8 + g;
                mma_tf32(acc[nf], a, Ws[w0 + col], Ws[w1 + col]);
            }
        }

        size_t rg0 = (size_t)(row0 + rowA), rg1 = rg0 + 8;
        #pragma unroll
        for (int nf = 0; nf < 4; nf++) {
            int mcol = nt*64 + half*32 + nf*8 + 2*tg;
            float b0 = bo[mcol], b1 = bo[mcol + 1];
            float2 x0 = *(const float2*)(g_xt + rg0*256 + mcol);
            float2 x1 = *(const float2*)(g_xt + rg1*256 + mcol);
            *(float2*)(g_xattn + rg0*256 + mcol) =
                make_float2(acc[nf][0] + b0 + x0.x, acc[nf][1] + b1 + x0.y);
            *(float2*)(g_xattn + rg1*256 + mcol) =
                make_float2(acc[nf][2] + b0 + x1.x, acc[nf][3] + b1 + x1.y);
        }
    }
}

// ---------------------------------------------------------------------------
// Kernel 1: normalize prototypes
// ---------------------------------------------------------------------------
__global__ void protonorm_kernel(const float* __restrict__ prot) {
    int r = blockIdx.x;
    int t = threadIdx.x;
    float v = prot[r*256 + t];
    float sq = v * v;
    #pragma unroll
    for (int off = 16; off > 0; off >>= 1)
        sq += __shfl_down_sync(0xffffffffu, sq, off);
    __shared__ float red[8];
    if ((t & 31) == 0) red[t >> 5] = sq;
    __syncthreads();
    __shared__ float rn;
    if (t == 0) {
        float sum = 0.f;
        #pragma unroll
        for (int i = 0; i < 8; i++) sum += red[i];
        rn = rsqrtf(sum);
    }
    __syncthreads();
    g_protn[r*256 + t] = v * rn;
}

// ---------------------------------------------------------------------------
// Kernel 2: instance-norm + dot + argmax -> hard idx
// ---------------------------------------------------------------------------
__global__ __launch_bounds__(256) void assign_kernel() {
    int p = blockIdx.x, n = blockIdx.y;
    extern __shared__ float smf[];
    float* Xs = smf;
    float* P  = Xs + 16384;
    float* MU = P + 1024;
    float* RS = MU + 256;
    int t = threadIdx.x;
    const float* src = g_xt + (size_t)(n*16 + p) * 16384;
    for (int i = t; i < 16384; i += 256) Xs[i] = src[i];
    const float* psrc = g_protn + p*1024;
    for (int i = t; i < 1024; i += 256) P[i] = psrc[i];
    __syncthreads();

    {
        float s1 = 0.f, s2 = 0.f;
        #pragma unroll
        for (int s = 0; s < 64; s++) {
            float v = Xs[s*256 + t];
            s1 += v; s2 += v*v;
        }
        float mu = s1 * 0.015625f;
        float var = s2 * 0.015625f - mu*mu;
        MU[t] = mu;
        RS[t] = rsqrtf(var + 1e-5f);
    }
    __syncthreads();

    int w = t >> 5, lane = t & 31;
    #pragma unroll
    for (int it = 0; it < 8; it++) {
        int s = w*8 + it;
        float d0 = 0.f, d1 = 0.f, d2 = 0.f, d3 = 0.f;
        #pragma unroll
        for (int cc = 0; cc < 8; cc++) {
            int c = lane + 32*cc;
            float y = (Xs[s*256 + c] - MU[c]) * RS[c];
            d0 = fmaf(y, P[c],       d0);
            d1 = fmaf(y, P[256 + c], d1);
            d2 = fmaf(y, P[512 + c], d2);
            d3 = fmaf(y, P[768 + c], d3);
        }
        #pragma unroll
        for (int off = 16; off > 0; off >>= 1) {
            d0 += __shfl_down_sync(0xffffffffu, d0, off);
            d1 += __shfl_down_sync(0xffffffffu, d1, off);
            d2 += __shfl_down_sync(0xffffffffu, d2, off);
            d3 += __shfl_down_sync(0xffffffffu, d3, off);
        }
        if (lane == 0) {
            int best = 0; float bv = d0;
            if (d1 > bv) { bv = d1; best = 1; }
            if (d2 > bv) { bv = d2; best = 2; }
            if (d3 > bv) { bv = d3; best = 3; }
            g_idx[(p*64 + n)*64 + s] = (unsigned char)best;
        }
    }
}

// ---------------------------------------------------------------------------
// Kernel 3: mode over parts -> cluster_indices (as float)
// ---------------------------------------------------------------------------
__global__ void mode_kernel(float* __restrict__ outci) {
    int id = blockIdx.x*256 + threadIdx.x;
    if (id >= NN*SS) return;
    int n = id >> 6, s = id & 63;
    int c0 = 0, c1 = 0, c2 = 0, c3 = 0;
    #pragma unroll
    for (int p = 0; p < 16; p++) {
        int a = g_idx[(p*64 + n)*64 + s];
        c0 += (a == 0); c1 += (a == 1); c2 += (a == 2); c3 += (a == 3);
    }
    int best = 0, bc = c0;
    if (c1 > bc) { bc = c1; best = 1; }
    if (c2 > bc) { bc = c2; best = 2; }
    if (c3 > bc) { bc = c3; best = 3; }
    outci[id] = (float)best;
}

// ---------------------------------------------------------------------------
// Kernel 5: scatter-max pooling
// ---------------------------------------------------------------------------
__global__ __launch_bounds__(256) void scatter_kernel() {
    int p = blockIdx.x, n = blockIdx.y, t = threadIdx.x;
    __shared__ unsigned char ids[64];
    if (t < 64) ids[t] = g_idx[(p*64 + n)*64 + t];
    __syncthreads();
    int c0 = 0, c1 = 0, c2 = 0, c3 = 0;
    #pragma unroll 8
    for (int s = 0; s < 64; s++) {
        int a = ids[s];
        c0 += (a == 0); c1 += (a == 1); c2 += (a == 2); c3 += (a == 3);
    }
    const float* src = g_xattn + (size_t)(n*16 + p)*16384 + t;
    float m0 = -3.402823466e38f, m1 = m0, m2 = m0, m3 = m0;
    #pragma unroll 8
    for (int s = 0; s < 64; s++) {
        float v = src[s*256];
        int a = ids[s];
        if (a == 0) m0 = fmaxf(m0, v);
        else if (a == 1) m1 = fmaxf(m1, v);
        else if (a == 2) m2 = fmaxf(m2, v);
        else m3 = fmaxf(m3, v);
    }
    if (c0 < 64) m0 = fmaxf(m0, 0.f);
    if (c1 < 64) m1 = fmaxf(m1, 0.f);
    if (c2 < 64) m2 = fmaxf(m2, 0.f);
    if (c3 < 64) m3 = fmaxf(m3, 0.f);
    float* dst = g_clustered + (size_t)(p*64 + n)*1024 + t;
    dst[0]   = m0;
    dst[256] = m1;
    dst[512] = m2;
    dst[768] = m3;
}

// ---------------------------------------------------------------------------
// Kernel 6: per-part FC
// ---------------------------------------------------------------------------
__global__ __launch_bounds__(256) void fc_kernel(const float* __restrict__ fcb,
                                                 float* __restrict__ out) {
    int p = blockIdx.x, n0 = blockIdx.y * 16, t = threadIdx.x;
    extern __shared__ float cl[];
    for (int nn = 0; nn < 16; nn++) {
        const float* src = g_clustered + (size_t)(p*64 + n0 + nn)*1024;
        for (int i = t; i < 1024; i += 256) cl[nn*1024 + i] = src[i];
    }
    __syncthreads();
    int o0 = t & 63, g = t >> 6;
    float acc[4][4];
    #pragma unroll
    for (int a = 0; a < 4; a++)
        #pragma unroll
        for (int bb = 0; bb < 4; bb++) acc[a][bb] = 0.f;
    const float* F = fcb + (size_t)p*1024*256 + o0;
    for (int kc = 0; kc < 1024; kc++) {
        float wv[4], cv[4];
        #pragma unroll
        for (int bb = 0; bb < 4; bb++) wv[bb] = F[(size_t)kc*256 + 64*bb];
        #pragma unroll
        for (int a = 0; a < 4; a++) cv[a] = cl[(g*4 + a)*1024 + kc];
        #pragma unroll
        for (int a = 0; a < 4; a++)
            #pragma unroll
            for (int bb = 0; bb < 4; bb++)
                acc[a][bb] = fmaf(cv[a], wv[bb], acc[a][bb]);
    }
    #pragma unroll
    for (int a = 0; a < 4; a++) {
        int n = n0 + g*4 + a;
        #pragma unroll
        for (int bb = 0; bb < 4; bb++) {
            int o = o0 + 64*bb;
            out[(size_t)n*4096 + o*16 + p] = acc[a][bb];
        }
    }
}

// ---------------------------------------------------------------------------
extern "C" void kernel_launch(void* const* d_in, const int* in_sizes, int n_in,
                              void* d_out, int out_size) {
    const float* x    = (const float*)d_in[0];
    const float* prot = (const float*)d_in[1];
    const float* Wq   = (const float*)d_in[2];
    const float* bq   = (const float*)d_in[3];
    const float* Wk   = (const float*)d_in[4];
    const float* bk   = (const float*)d_in[5];
    const float* Wv   = (const float*)d_in[6];
    const float* bv   = (const float*)d_in[7];
    const float* Wo   = (const float*)d_in[8];
    const float* bo   = (const float*)d_in[9];
    const float* fcb  = (const float*)d_in[10];
    float* out = (float*)d_out;

    cudaFuncSetAttribute(qkv_kernel,  cudaFuncAttributeMaxDynamicSharedMemorySize, QK_U32*4);
    cudaFuncSetAttribute(kout_kernel, cudaFuncAttributeMaxDynamicSharedMemorySize, QK_U32*4);
    cudaFuncSetAttribute(core_kernel, cudaFuncAttributeMaxDynamicSharedMemorySize, C_U32*4);
    cudaFuncSetAttribute(assign_kernel, cudaFuncAttributeMaxDynamicSharedMemorySize, 71680);
    cudaFuncSetAttribute(fc_kernel, cudaFuncAttributeMaxDynamicSharedMemorySize, 65536);

    transpose_kernel<<<NN*SS, 256>>>(x);
    packw_kernel<<<dim3(256, 4), 256>>>(Wq, Wk, Wv, Wo);
    packx_kernel<<<NR*64/256, 256>>>();
    qkv_kernel<<<512, 512, QK_U32*4>>>(bq, bk, bv);
    core_kernel<<<dim3(NB, 4), 128, C_U32*4>>>();
    kout_kernel<<<512, 512, QK_U32*4>>>(bo);
    protonorm_kernel<<<PP*KK, 256>>>(prot);
    assign_kernel<<<dim3(PP, NN), 256, 71680>>>();
    if (out_size >= NN*CC*PP + NN*SS)
        mode_kernel<<<16, 256>>>(out + NN*CC*PP);
    scatter_kernel<<<dim3(PP, NN), 256>>>();
    fc_kernel<<<dim3(PP, 4), 256, 65536>>>(fcb, out);
}

// round 12
// speedup vs baseline: 1.2988x; 1.0867x over previous
#include <cuda_runtime.h>
#include <cuda_bf16.h>
#include <math.h>

// Problem constants
#define NN 64
#define CC 256
#define SS 64
#define PP 16
#define KK 4
#define NB (NN*PP)   // 1024 attention batches
#define NR (NB*SS)   // 65536 rows

// Scratch (no cudaMalloc allowed)
__device__ float g_xt[NR*CC];           // (n,p,s,c) fp32
__device__ float g_xattn[NR*CC];        // attention out + residual
__device__ float g_protn[PP*KK*CC];
__device__ float g_clustered[PP*NN*KK*CC];
__device__ unsigned char g_idx[PP*NN*SS];
// tf32 planes (u32 bit patterns)
__device__ unsigned g_xq[NR*CC];        // X tf32
__device__ unsigned g_q [NR*CC];        // Q tf32
__device__ unsigned g_k [NR*CC];        // K tf32
__device__ unsigned g_vq[NR*CC];        // V tf32
__device__ unsigned g_h [NR*CC];        // head-concat out tf32
// tf32 weights [ws][k][n], ws = q,k,v,o
__device__ unsigned g_wt[4*256*256];

// ---------------------------------------------------------------------------
// helpers
// ---------------------------------------------------------------------------
__device__ __forceinline__ unsigned f2tf(float f) {
    unsigned u;
    asm("cvt.rna.tf32.f32 %0, %1;" : "=r"(u) : "f"(f));
    return u;
}

__device__ __forceinline__ void mma_tf32(float c[4], const unsigned a[4],
                                         unsigned b0, unsigned b1) {
    asm volatile(
        "mma.sync.aligned.m16n8k8.row.col.f32.tf32.tf32.f32 "
        "{%0,%1,%2,%3},{%4,%5,%6,%7},{%8,%9},{%0,%1,%2,%3};"
        : "+f"(c[0]), "+f"(c[1]), "+f"(c[2]), "+f"(c[3])
        : "r"(a[0]), "r"(a[1]), "r"(a[2]), "r"(a[3]), "r"(b0), "r"(b1));
}

// ---------------------------------------------------------------------------
// Kernel P1: weights -> tf32
// ---------------------------------------------------------------------------
__global__ void packw_kernel(const float* __restrict__ Wq, const float* __restrict__ Wk,
                             const float* __restrict__ Wv, const float* __restrict__ Wo) {
    int ws = blockIdx.y;
    int i = blockIdx.x*256 + threadIdx.x;
    const float* W = (ws == 0) ? Wq : (ws == 1) ? Wk : (ws == 2) ? Wv : Wo;
    g_wt[ws*65536 + i] = f2tf(W[i]);
}

// ---------------------------------------------------------------------------
// Kernel 0: transpose x (n,c,s,p) -> g_xt (n,p,s,c) + tf32 pack fused
// ---------------------------------------------------------------------------
__global__ void transpose_kernel(const float* __restrict__ x) {
    __shared__ float tile[256*17];
    int bx = blockIdx.x;
    int n = bx >> 6, s = bx & 63;
    int t = threadIdx.x;
    const float* src = x + (size_t)n*262144 + (size_t)s*16;
    #pragma unroll
    for (int w = 0; w < 16; w++) {
        int i = t + w*256;
        int c = i >> 4, pp = i & 15;
        tile[c*17 + pp] = src[(size_t)c*1024 + pp];
    }
    __syncthreads();
    float* dst = g_xt + (size_t)n*262144 + (size_t)s*256;
    unsigned* dq = g_xq + (size_t)n*262144 + (size_t)s*256;
    #pragma unroll
    for (int w = 0; w < 16; w++) {
        float v = tile[t*17 + w];
        dst[(size_t)w*16384 + t] = v;
        dq[(size_t)w*16384 + t] = f2tf(v);
    }
}

// ---------------------------------------------------------------------------
// qkv: [65536 x 256] x [256 x 768] tf32; 512 CTAs x 512 thr, SW-pipelined
// smem u32: Xs 128 rows stride 260 (33280) + Ws 256 k stride 72 (18432)
// ---------------------------------------------------------------------------
#define QK_WS 33280
#define QK_U32 51712    // 206848 B

__global__ __launch_bounds__(512, 1) void qkv_kernel(
    const float* __restrict__ bq, const float* __restrict__ bk,
    const float* __restrict__ bv) {
    extern __shared__ unsigned sm[];
    unsigned* Xs = sm;
    unsigned* Ws = sm + QK_WS;
    int t = threadIdx.x;
    int w = t >> 5, lane = t & 31;
    int g = lane >> 2, tg = lane & 3;
    int row0 = blockIdx.x * 128;

    {
        const uint4* xs = (const uint4*)(g_xq + (size_t)row0*256);
        for (int idx = t; idx < 8192; idx += 512) {
            int r = idx >> 6, c4 = idx & 63;
            *(uint4*)(Xs + r*260 + 4*c4) = xs[idx];
        }
    }

    int mt = w >> 1, half = w & 1;
    int rowA = mt*16 + g;

    for (int nt = 0; nt < 12; nt++) {
        int sel = nt >> 2, nto = nt & 3;
        __syncthreads();
        {
            const unsigned* wsrc = g_wt + sel*65536 + nto*64;
            for (int idx = t; idx < 4096; idx += 512) {
                int k = idx >> 4, c4 = idx & 15;
                *(uint4*)(Ws + k*72 + 4*c4) = *(const uint4*)(wsrc + k*256 + 4*c4);
            }
        }
        __syncthreads();

        float acc[4][4];
        #pragma unroll
        for (int i = 0; i < 4; i++)
            #pragma unroll
            for (int j = 0; j < 4; j++) acc[i][j] = 0.f;

        unsigned aP[2][4], bP[2][4][2];
        {
            int ab = rowA*260 + tg;
            aP[0][0] = Xs[ab];     aP[0][1] = Xs[ab + 8*260];
            aP[0][2] = Xs[ab + 4]; aP[0][3] = Xs[ab + 8*260 + 4];
            int w0 = tg*72, w1 = (tg + 4)*72;
            #pragma unroll
            for (int nf = 0; nf < 4; nf++) {
                int col = half*32 + nf*8 + g;
                bP[0][nf][0] = Ws[w0 + col]; bP[0][nf][1] = Ws[w1 + col];
            }
        }
        #pragma unroll
        for (int s = 0; s < 32; s++) {
            int c = s & 1, nx = c ^ 1;
            if (s < 31) {
                int ab = rowA*260 + 8*(s+1) + tg;
                aP[nx][0] = Xs[ab];     aP[nx][1] = Xs[ab + 8*260];
                aP[nx][2] = Xs[ab + 4]; aP[nx][3] = Xs[ab + 8*260 + 4];
                int w0 = (8*(s+1) + tg)*72, w1 = (8*(s+1) + tg + 4)*72;
                #pragma unroll
                for (int nf = 0; nf < 4; nf++) {
                    int col = half*32 + nf*8 + g;
                    bP[nx][nf][0] = Ws[w0 + col]; bP[nx][nf][1] = Ws[w1 + col];
                }
            }
            #pragma unroll
            for (int nf = 0; nf < 4; nf++)
                mma_tf32(acc[nf], aP[c], bP[c][nf][0], bP[c][nf][1]);
        }

        const float* bias = (sel == 0) ? bq : (sel == 1) ? bk : bv;
        unsigned* dst = (sel == 0) ? g_q : (sel == 1) ? g_k : g_vq;
        size_t rg0 = (size_t)(row0 + rowA), rg1 = rg0 + 8;
        #pragma unroll
        for (int nf = 0; nf < 4; nf++) {
            int mcol = nto*64 + half*32 + nf*8 + 2*tg;
            float b0 = bias[mcol], b1 = bias[mcol + 1];
            uint2 o0, o1;
            o0.x = f2tf(acc[nf][0] + b0); o0.y = f2tf(acc[nf][1] + b1);
            o1.x = f2tf(acc[nf][2] + b0); o1.y = f2tf(acc[nf][3] + b1);
            *(uint2*)(dst + rg0*256 + mcol) = o0;
            *(uint2*)(dst + rg1*256 + mcol) = o1;
        }
    }
}

// ---------------------------------------------------------------------------
// core: per (batch, head): scores + WARP-LOCAL softmax (register transpose via
// quad shuffles) + S@V.  128 thr, 4 CTAs/SM, ONE __syncthreads.
// smem u32: Qs@0, Ks, Vt  (each 64 x 68)
// ---------------------------------------------------------------------------
#define C_Q 0
#define C_K (64*68)
#define C_V (2*64*68)
#define C_U32 (3*64*68)    // 13056 u32 = 52224 B

__global__ __launch_bounds__(128, 4) void core_kernel() {
    extern __shared__ unsigned sm[];
    int t = threadIdx.x;
    int w = t >> 5, lane = t & 31;
    int g = lane >> 2, tg = lane & 3;
    int b = blockIdx.x, h = blockIdx.y;
    size_t rbase = (size_t)b * 64;

    for (int idx = t; idx < 1024; idx += 128) {
        int s = idx >> 4, c4 = idx & 15;
        *(uint4*)(sm + C_Q + s*68 + 4*c4) = *(const uint4*)(g_q + (rbase + s)*256 + h*64 + 4*c4);
        *(uint4*)(sm + C_K + s*68 + 4*c4) = *(const uint4*)(g_k + (rbase + s)*256 + h*64 + 4*c4);
    }
    for (int idx = t; idx < 4096; idx += 128) {
        int s = idx >> 6, d = idx & 63;
        sm[C_V + d*68 + s] = g_vq[(rbase + s)*256 + h*64 + d];   // V transposed
    }
    __syncthreads();

    int rowA = w*16 + g;

    // ---- scores = Q K^T ----
    float sc[8][4];
    #pragma unroll
    for (int i = 0; i < 8; i++) { sc[i][0] = sc[i][1] = sc[i][2] = sc[i][3] = 0.f; }
    #pragma unroll
    for (int s8 = 0; s8 < 8; s8++) {
        unsigned a[4];
        int ab = C_Q + rowA*68 + 8*s8 + tg;
        a[0] = sm[ab]; a[1] = sm[ab + 8*68]; a[2] = sm[ab + 4]; a[3] = sm[ab + 8*68 + 4];
        #pragma unroll
        for (int nf = 0; nf < 8; nf++) {
            int bb = C_K + (nf*8 + g)*68 + 8*s8 + tg;
            mma_tf32(sc[nf], a, sm[bb], sm[bb + 4]);
        }
    }

    // ---- warp-local causal softmax (rows rowA, rowA+8; quad = row) ----
    const float NI = -3.402823466e38f;
    int rA = rowA, rB = rowA + 8;
    float mA = NI, mB = NI;
    #pragma unroll
    for (int nf = 0; nf < 8; nf++) {
        int c0 = nf*8 + 2*tg, c1 = c0 + 1;
        sc[nf][0] = (c0 <= rA) ? sc[nf][0]*0.125f : NI;
        sc[nf][1] = (c1 <= rA) ? sc[nf][1]*0.125f : NI;
        sc[nf][2] = (c0 <= rB) ? sc[nf][2]*0.125f : NI;
        sc[nf][3] = (c1 <= rB) ? sc[nf][3]*0.125f : NI;
        mA = fmaxf(mA, fmaxf(sc[nf][0], sc[nf][1]));
        mB = fmaxf(mB, fmaxf(sc[nf][2], sc[nf][3]));
    }
    mA = fmaxf(mA, __shfl_xor_sync(0xffffffffu, mA, 1));
    mA = fmaxf(mA, __shfl_xor_sync(0xffffffffu, mA, 2));
    mB = fmaxf(mB, __shfl_xor_sync(0xffffffffu, mB, 1));
    mB = fmaxf(mB, __shfl_xor_sync(0xffffffffu, mB, 2));
    float sA = 0.f, sB = 0.f;
    #pragma unroll
    for (int nf = 0; nf < 8; nf++) {
        int c0 = nf*8 + 2*tg, c1 = c0 + 1;
        float e0 = (c0 <= rA) ? __expf(sc[nf][0] - mA) : 0.f;
        float e1 = (c1 <= rA) ? __expf(sc[nf][1] - mA) : 0.f;
        float e2 = (c0 <= rB) ? __expf(sc[nf][2] - mB) : 0.f;
        float e3 = (c1 <= rB) ? __expf(sc[nf][3] - mB) : 0.f;
        sA += e0 + e1; sB += e2 + e3;
        sc[nf][0] = e0; sc[nf][1] = e1; sc[nf][2] = e2; sc[nf][3] = e3;
    }
    sA += __shfl_xor_sync(0xffffffffu, sA, 1);
    sA += __shfl_xor_sync(0xffffffffu, sA, 2);
    sB += __shfl_xor_sync(0xffffffffu, sB, 1);
    sB += __shfl_xor_sync(0xffffffffu, sB, 2);
    float iA = 1.f / sA, iB = 1.f / sB;
    unsigned P[8][4];
    #pragma unroll
    for (int nf = 0; nf < 8; nf++) {
        P[nf][0] = f2tf(sc[nf][0] * iA);
        P[nf][1] = f2tf(sc[nf][1] * iA);
        P[nf][2] = f2tf(sc[nf][2] * iB);
        P[nf][3] = f2tf(sc[nf][3] * iB);
    }

    // ---- S @ V : A-frags from P via quad transpose shuffles ----
    float ha[8][4];
    #pragma unroll
    for (int i = 0; i < 8; i++) { ha[i][0] = ha[i][1] = ha[i][2] = ha[i][3] = 0.f; }
    int srcLo = (lane & 28) | (tg >> 1);
    int srcHi = srcLo + 2;
    bool odd = (tg & 1);
    #pragma unroll
    for (int s8 = 0; s8 < 8; s8++) {
        unsigned q00 = __shfl_sync(0xffffffffu, P[s8][0], srcLo);
        unsigned q01 = __shfl_sync(0xffffffffu, P[s8][1], srcLo);
        unsigned q10 = __shfl_sync(0xffffffffu, P[s8][2], srcLo);
        unsigned q11 = __shfl_sync(0xffffffffu, P[s8][3], srcLo);
        unsigned r00 = __shfl_sync(0xffffffffu, P[s8][0], srcHi);
        unsigned r01 = __shfl_sync(0xffffffffu, P[s8][1], srcHi);
        unsigned r10 = __shfl_sync(0xffffffffu, P[s8][2], srcHi);
        unsigned r11 = __shfl_sync(0xffffffffu, P[s8][3], srcHi);
        unsigned a[4];
        a[0] = odd ? q01 : q00;
        a[1] = odd ? q11 : q10;
        a[2] = odd ? r01 : r00;
        a[3] = odd ? r11 : r10;
        #pragma unroll
        for (int nf = 0; nf < 8; nf++) {
            int bb = C_V + (nf*8 + g)*68 + 8*s8 + tg;
            mma_tf32(ha[nf], a, sm[bb], sm[bb + 4]);
        }
    }

    #pragma unroll
    for (int nf = 0; nf < 8; nf++) {
        int gcol = h*64 + nf*8 + 2*tg;
        uint2 o0, o1;
        o0.x = f2tf(ha[nf][0]); o0.y = f2tf(ha[nf][1]);
        o1.x = f2tf(ha[nf][2]); o1.y = f2tf(ha[nf][3]);
        *(uint2*)(g_h + (rbase + rowA)*256 + gcol) = o0;
        *(uint2*)(g_h + (rbase + rowA + 8)*256 + gcol) = o1;
    }
}

// ---------------------------------------------------------------------------
// kout: [65536 x 256] x Wo + bo + residual, tf32, SW-pipelined
// ---------------------------------------------------------------------------
__global__ __launch_bounds__(512, 1) void kout_kernel(const float* __restrict__ bo) {
    extern __shared__ unsigned sm[];
    unsigned* Xs = sm;
    unsigned* Ws = sm + QK_WS;
    int t = threadIdx.x;
    int w = t >> 5, lane = t & 31;
    int g = lane >> 2, tg = lane & 3;
    int row0 = blockIdx.x * 128;

    {
        const uint4* xs = (const uint4*)(g_h + (size_t)row0*256);
        for (int idx = t; idx < 8192; idx += 512) {
            int r = idx >> 6, c4 = idx & 63;
            *(uint4*)(Xs + r*260 + 4*c4) = xs[idx];
        }
    }

    int mt = w >> 1, half = w & 1;
    int rowA = mt*16 + g;

    for (int nt = 0; nt < 4; nt++) {
        __syncthreads();
        {
            const unsigned* wsrc = g_wt + 3*65536 + nt*64;
            for (int idx = t; idx < 4096; idx += 512) {
                int k = idx >> 4, c4 = idx & 15;
                *(uint4*)(Ws + k*72 + 4*c4) = *(const uint4*)(wsrc + k*256 + 4*c4);
            }
        }
        __syncthreads();

        float acc[4][4];
        #pragma unroll
        for (int i = 0; i < 4; i++)
            #pragma unroll
            for (int j = 0; j < 4; j++) acc[i][j] = 0.f;

        unsigned aP[2][4], bP[2][4][2];
        {
            int ab = rowA*260 + tg;
            aP[0][0] = Xs[ab];     aP[0][1] = Xs[ab + 8*260];
            aP[0][2] = Xs[ab + 4]; aP[0][3] = Xs[ab + 8*260 + 4];
            int w0 = tg*72, w1 = (tg + 4)*72;
            #pragma unroll
            for (int nf = 0; nf < 4; nf++) {
                int col = half*32 + nf*8 + g;
                bP[0][nf][0] = Ws[w0 + col]; bP[0][nf][1] = Ws[w1 + col];
            }
        }
        #pragma unroll
        for (int s = 0; s < 32; s++) {
            int c = s & 1, nx = c ^ 1;
            if (s < 31) {
                int ab = rowA*260 + 8*(s+1) + tg;
                aP[nx][0] = Xs[ab];     aP[nx][1] = Xs[ab + 8*260];
                aP[nx][2] = Xs[ab + 4]; aP[nx][3] = Xs[ab + 8*260 + 4];
                int w0 = (8*(s+1) + tg)*72, w1 = (8*(s+1) + tg + 4)*72;
                #pragma unroll
                for (int nf = 0; nf < 4; nf++) {
                    int col = half*32 + nf*8 + g;
                    bP[nx][nf][0] = Ws[w0 + col]; bP[nx][nf][1] = Ws[w1 + col];
                }
            }
            #pragma unroll
            for (int nf = 0; nf < 4; nf++)
                mma_tf32(acc[nf], aP[c], bP[c][nf][0], bP[c][nf][1]);
        }

        size_t rg0 = (size_t)(row0 + rowA), rg1 = rg0 + 8;
        #pragma unroll
        for (int nf = 0; nf < 4; nf++) {
            int mcol = nt*64 + half*32 + nf*8 + 2*tg;
            float b0 = bo[mcol], b1 = bo[mcol + 1];
            float2 x0 = *(const float2*)(g_xt + rg0*256 + mcol);
            float2 x1 = *(const float2*)(g_xt + rg1*256 + mcol);
            *(float2*)(g_xattn + rg0*256 + mcol) =
                make_float2(acc[nf][0] + b0 + x0.x, acc[nf][1] + b1 + x0.y);
            *(float2*)(g_xattn + rg1*256 + mcol) =
                make_float2(acc[nf][2] + b0 + x1.x, acc[nf][3] + b1 + x1.y);
        }
    }
}

// ---------------------------------------------------------------------------
// Kernel 1: normalize prototypes
// ---------------------------------------------------------------------------
__global__ void protonorm_kernel(const float* __restrict__ prot) {
    int r = blockIdx.x;
    int t = threadIdx.x;
    float v = prot[r*256 + t];
    float sq = v * v;
    #pragma unroll
    for (int off = 16; off > 0; off >>= 1)
        sq += __shfl_down_sync(0xffffffffu, sq, off);
    __shared__ float red[8];
    if ((t & 31) == 0) red[t >> 5] = sq;
    __syncthreads();
    __shared__ float rn;
    if (t == 0) {
        float sum = 0.f;
        #pragma unroll
        for (int i = 0; i < 8; i++) sum += red[i];
        rn = rsqrtf(sum);
    }
    __syncthreads();
    g_protn[r*256 + t] = v * rn;
}

// ---------------------------------------------------------------------------
// Kernel 2: instance-norm + dot + argmax -> hard idx
// ---------------------------------------------------------------------------
__global__ __launch_bounds__(256) void assign_kernel() {
    int p = blockIdx.x, n = blockIdx.y;
    extern __shared__ float smf[];
    float* Xs = smf;
    float* P  = Xs + 16384;
    float* MU = P + 1024;
    float* RS = MU + 256;
    int t = threadIdx.x;
    const float* src = g_xt + (size_t)(n*16 + p) * 16384;
    for (int i = t; i < 16384; i += 256) Xs[i] = src[i];
    const float* psrc = g_protn + p*1024;
    for (int i = t; i < 1024; i += 256) P[i] = psrc[i];
    __syncthreads();

    {
        float s1 = 0.f, s2 = 0.f;
        #pragma unroll
        for (int s = 0; s < 64; s++) {
            float v = Xs[s*256 + t];
            s1 += v; s2 += v*v;
        }
        float mu = s1 * 0.015625f;
        float var = s2 * 0.015625f - mu*mu;
        MU[t] = mu;
        RS[t] = rsqrtf(var + 1e-5f);
    }
    __syncthreads();

    int w = t >> 5, lane = t & 31;
    #pragma unroll
    for (int it = 0; it < 8; it++) {
        int s = w*8 + it;
        float d0 = 0.f, d1 = 0.f, d2 = 0.f, d3 = 0.f;
        #pragma unroll
        for (int cc = 0; cc < 8; cc++) {
            int c = lane + 32*cc;
            float y = (Xs[s*256 + c] - MU[c]) * RS[c];
            d0 = fmaf(y, P[c],       d0);
            d1 = fmaf(y, P[256 + c], d1);
            d2 = fmaf(y, P[512 + c], d2);
            d3 = fmaf(y, P[768 + c], d3);
        }
        #pragma unroll
        for (int off = 16; off > 0; off >>= 1) {
            d0 += __shfl_down_sync(0xffffffffu, d0, off);
            d1 += __shfl_down_sync(0xffffffffu, d1, off);
            d2 += __shfl_down_sync(0xffffffffu, d2, off);
            d3 += __shfl_down_sync(0xffffffffu, d3, off);
        }
        if (lane == 0) {
            int best = 0; float bv = d0;
            if (d1 > bv) { bv = d1; best = 1; }
            if (d2 > bv) { bv = d2; best = 2; }
            if (d3 > bv) { bv = d3; best = 3; }
            g_idx[(p*64 + n)*64 + s] = (unsigned char)best;
        }
    }
}

// ---------------------------------------------------------------------------
// Kernel 3: mode over parts -> cluster_indices (as float)
// ---------------------------------------------------------------------------
__global__ void mode_kernel(float* __restrict__ outci) {
    int id = blockIdx.x*256 + threadIdx.x;
    if (id >= NN*SS) return;
    int n = id >> 6, s = id & 63;
    int c0 = 0, c1 = 0, c2 = 0, c3 = 0;
    #pragma unroll
    for (int p = 0; p < 16; p++) {
        int a = g_idx[(p*64 + n)*64 + s];
        c0 += (a == 0); c1 += (a == 1); c2 += (a == 2); c3 += (a == 3);
    }
    int best = 0, bc = c0;
    if (c1 > bc) { bc = c1; best = 1; }
    if (c2 > bc) { bc = c2; best = 2; }
    if (c3 > bc) { bc = c3; best = 3; }
    outci[id] = (float)best;
}

// ---------------------------------------------------------------------------
// Kernel 5: scatter-max pooling
// ---------------------------------------------------------------------------
__global__ __launch_bounds__(256) void scatter_kernel() {
    int p = blockIdx.x, n = blockIdx.y, t = threadIdx.x;
    __shared__ unsigned char ids[64];
    if (t < 64) ids[t] = g_idx[(p*64 + n)*64 + t];
    __syncthreads();
    int c0 = 0, c1 = 0, c2 = 0, c3 = 0;
    #pragma unroll 8
    for (int s = 0; s < 64; s++) {
        int a = ids[s];
        c0 += (a == 0); c1 += (a == 1); c2 += (a == 2); c3 += (a == 3);
    }
    const float* src = g_xattn + (size_t)(n*16 + p)*16384 + t;
    float m0 = -3.402823466e38f, m1 = m0, m2 = m0, m3 = m0;
    #pragma unroll 8
    for (int s = 0; s < 64; s++) {
        float v = src[s*256];
        int a = ids[s];
        if (a == 0) m0 = fmaxf(m0, v);
        else if (a == 1) m1 = fmaxf(m1, v);
        else if (a == 2) m2 = fmaxf(m2, v);
        else m3 = fmaxf(m3, v);
    }
    if (c0 < 64) m0 = fmaxf(m0, 0.f);
    if (c1 < 64) m1 = fmaxf(m1, 0.f);
    if (c2 < 64) m2 = fmaxf(m2, 0.f);
    if (c3 < 64) m3 = fmaxf(m3, 0.f);
    float* dst = g_clustered + (size_t)(p*64 + n)*1024 + t;
    dst[0]   = m0;
    dst[256] = m1;
    dst[512] = m2;
    dst[768] = m3;
}

// ---------------------------------------------------------------------------
// Kernel 6: per-part FC
// ---------------------------------------------------------------------------
__global__ __launch_bounds__(256) void fc_kernel(const float* __restrict__ fcb,
                                                 float* __restrict__ out) {
    int p = blockIdx.x, n0 = blockIdx.y * 16, t = threadIdx.x;
    extern __shared__ float cl[];
    for (int nn = 0; nn < 16; nn++) {
        const float* src = g_clustered + (size_t)(p*64 + n0 + nn)*1024;
        for (int i = t; i < 1024; i += 256) cl[nn*1024 + i] = src[i];
    }
    __syncthreads();
    int o0 = t & 63, g = t >> 6;
    float acc[4][4];
    #pragma unroll
    for (int a = 0; a < 4; a++)
        #pragma unroll
        for (int bb = 0; bb < 4; bb++) acc[a][bb] = 0.f;
    const float* F = fcb + (size_t)p*1024*256 + o0;
    for (int kc = 0; kc < 1024; kc++) {
        float wv[4], cv[4];
        #pragma unroll
        for (int bb = 0; bb < 4; bb++) wv[bb] = F[(size_t)kc*256 + 64*bb];
        #pragma unroll
        for (int a = 0; a < 4; a++) cv[a] = cl[(g*4 + a)*1024 + kc];
        #pragma unroll
        for (int a = 0; a < 4; a++)
            #pragma unroll
            for (int bb = 0; bb < 4; bb++)
                acc[a][bb] = fmaf(cv[a], wv[bb], acc[a][bb]);
    }
    #pragma unroll
    for (int a = 0; a < 4; a++) {
        int n = n0 + g*4 + a;
        #pragma unroll
        for (int bb = 0; bb < 4; bb++) {
            int o = o0 + 64*bb;
            out[(size_t)n*4096 + o*16 + p] = acc[a][bb];
        }
    }
}

// ---------------------------------------------------------------------------
extern "C" void kernel_launch(void* const* d_in, const int* in_sizes, int n_in,
                              void* d_out, int out_size) {
    const float* x    = (const float*)d_in[0];
    const float* prot = (const float*)d_in[1];
    const float* Wq   = (const float*)d_in[2];
    const float* bq   = (const float*)d_in[3];
    const float* Wk   = (const float*)d_in[4];
    const float* bk   = (const float*)d_in[5];
    const float* Wv   = (const float*)d_in[6];
    const float* bv   = (const float*)d_in[7];
    const float* Wo   = (const float*)d_in[8];
    const float* bo   = (const float*)d_in[9];
    const float* fcb  = (const float*)d_in[10];
    float* out = (float*)d_out;

    cudaFuncSetAttribute(qkv_kernel,  cudaFuncAttributeMaxDynamicSharedMemorySize, QK_U32*4);
    cudaFuncSetAttribute(kout_kernel, cudaFuncAttributeMaxDynamicSharedMemorySize, QK_U32*4);
    cudaFuncSetAttribute(core_kernel, cudaFuncAttributeMaxDynamicSharedMemorySize, C_U32*4);
    cudaFuncSetAttribute(assign_kernel, cudaFuncAttributeMaxDynamicSharedMemorySize, 71680);
    cudaFuncSetAttribute(fc_kernel, cudaFuncAttributeMaxDynamicSharedMemorySize, 65536);

    transpose_kernel<<<NN*SS, 256>>>(x);
    packw_kernel<<<dim3(256, 4), 256>>>(Wq, Wk, Wv, Wo);
    qkv_kernel<<<512, 512, QK_U32*4>>>(bq, bk, bv);
    core_kernel<<<dim3(NB, 4), 128, C_U32*4>>>();
    kout_kernel<<<512, 512, QK_U32*4>>>(bo);
    protonorm_kernel<<<PP*KK, 256>>>(prot);
    assign_kernel<<<dim3(PP, NN), 256, 71680>>>();
    if (out_size >= NN*CC*PP + NN*SS)
        mode_kernel<<<16, 256>>>(out + NN*CC*PP);
    scatter_kernel<<<dim3(PP, NN), 256>>>();
    fc_kernel<<<dim3(PP, 4), 256, 65536>>>(fcb, out);
}

// round 14
// speedup vs baseline: 1.3696x; 1.0545x over previous
#include <cuda_runtime.h>
#include <cuda_bf16.h>
#include <math.h>

// Problem constants
#define NN 64
#define CC 256
#define SS 64
#define PP 16
#define KK 4
#define NB (NN*PP)   // 1024 attention batches
#define NR (NB*SS)   // 65536 rows

// Scratch (no cudaMalloc allowed)
__device__ float g_xt[NR*CC];           // (n,p,s,c) fp32
__device__ float g_xattn[NR*CC];        // attention out + residual
__device__ float g_protn[PP*KK*CC];
__device__ float g_clustered[PP*NN*KK*CC];
__device__ unsigned char g_idx[PP*NN*SS];
// tf32 planes (u32 bit patterns)
__device__ unsigned g_xq[NR*CC];        // X tf32
__device__ unsigned g_q [NR*CC];        // Q tf32
__device__ unsigned g_k [NR*CC];        // K tf32
__device__ unsigned g_vq[NR*CC];        // V tf32
__device__ unsigned g_h [NR*CC];        // head-concat out tf32
// tf32 weights [ws][k][n], ws = q,k,v,o
__device__ unsigned g_wt[4*256*256];

// ---------------------------------------------------------------------------
// helpers
// ---------------------------------------------------------------------------
__device__ __forceinline__ unsigned f2tf(float f) {
    unsigned u;
    asm("cvt.rna.tf32.f32 %0, %1;" : "=r"(u) : "f"(f));
    return u;
}

__device__ __forceinline__ void mma_tf32(float c[4], const unsigned a[4],
                                         unsigned b0, unsigned b1) {
    asm volatile(
        "mma.sync.aligned.m16n8k8.row.col.f32.tf32.tf32.f32 "
        "{%0,%1,%2,%3},{%4,%5,%6,%7},{%8,%9},{%0,%1,%2,%3};"
        : "+f"(c[0]), "+f"(c[1]), "+f"(c[2]), "+f"(c[3])
        : "r"(a[0]), "r"(a[1]), "r"(a[2]), "r"(a[3]), "r"(b0), "r"(b1));
}

// ---------------------------------------------------------------------------
// Kernel P1: weights -> tf32
// ---------------------------------------------------------------------------
__global__ void packw_kernel(const float* __restrict__ Wq, const float* __restrict__ Wk,
                             const float* __restrict__ Wv, const float* __restrict__ Wo) {
    int ws = blockIdx.y;
    int i = blockIdx.x*256 + threadIdx.x;
    const float* W = (ws == 0) ? Wq : (ws == 1) ? Wk : (ws == 2) ? Wv : Wo;
    g_wt[ws*65536 + i] = f2tf(W[i]);
}

// ---------------------------------------------------------------------------
// Kernel 0: transpose x (n,c,s,p) -> g_xt (n,p,s,c) + tf32 pack fused
// ---------------------------------------------------------------------------
__global__ void transpose_kernel(const float* __restrict__ x) {
    __shared__ float tile[256*17];
    int bx = blockIdx.x;
    int n = bx >> 6, s = bx & 63;
    int t = threadIdx.x;
    const float* src = x + (size_t)n*262144 + (size_t)s*16;
    #pragma unroll
    for (int w = 0; w < 16; w++) {
        int i = t + w*256;
        int c = i >> 4, pp = i & 15;
        tile[c*17 + pp] = src[(size_t)c*1024 + pp];
    }
    __syncthreads();
    float* dst = g_xt + (size_t)n*262144 + (size_t)s*256;
    unsigned* dq = g_xq + (size_t)n*262144 + (size_t)s*256;
    #pragma unroll
    for (int w = 0; w < 16; w++) {
        float v = tile[t*17 + w];
        dst[(size_t)w*16384 + t] = v;
        dq[(size_t)w*16384 + t] = f2tf(v);
    }
}

// ---------------------------------------------------------------------------
// qkv: [65536 x 256] x [256 x 768] tf32; 512 CTAs x 256 thr (8 warps)
// Each warp: 32 rows x 32 cols (M2 x N4 tiles) -> 256 B smem / mma.
// smem u32: Xs 128 rows stride 260 (33280) + Ws 256 k stride 72 (18432)
// ---------------------------------------------------------------------------
#define QK_WS 33280
#define QK_U32 51712    // 206848 B

__global__ __launch_bounds__(256, 1) void qkv_kernel(
    const float* __restrict__ bq, const float* __restrict__ bk,
    const float* __restrict__ bv) {
    extern __shared__ unsigned sm[];
    unsigned* Xs = sm;
    unsigned* Ws = sm + QK_WS;
    int t = threadIdx.x;
    int w = t >> 5, lane = t & 31;
    int g = lane >> 2, tg = lane & 3;
    int wm = w & 3, wn = w >> 2;      // 4 m-groups x 2 n-groups
    int row0 = blockIdx.x * 128;

    {
        const uint4* xs = (const uint4*)(g_xq + (size_t)row0*256);
        for (int idx = t; idx < 8192; idx += 256) {
            int r = idx >> 6, c4 = idx & 63;
            *(uint4*)(Xs + r*260 + 4*c4) = xs[idx];
        }
    }

    int rbase = wm*32 + g;            // mtile mi -> rows rbase+16*mi (+8)

    for (int nt = 0; nt < 12; nt++) {
        int sel = nt >> 2, nto = nt & 3;
        __syncthreads();
        {
            const unsigned* wsrc = g_wt + sel*65536 + nto*64;
            for (int idx = t; idx < 4096; idx += 256) {
                int k = idx >> 4, c4 = idx & 15;
                *(uint4*)(Ws + k*72 + 4*c4) = *(const uint4*)(wsrc + k*256 + 4*c4);
            }
        }
        __syncthreads();

        float acc[2][4][4];
        #pragma unroll
        for (int mi = 0; mi < 2; mi++)
            #pragma unroll
            for (int nf = 0; nf < 4; nf++)
                #pragma unroll
                for (int j = 0; j < 4; j++) acc[mi][nf][j] = 0.f;

        unsigned aP[2][2][4], bP[2][4][2];
        {
            #pragma unroll
            for (int mi = 0; mi < 2; mi++) {
                int ab = (rbase + 16*mi)*260 + tg;
                aP[0][mi][0] = Xs[ab];     aP[0][mi][1] = Xs[ab + 8*260];
                aP[0][mi][2] = Xs[ab + 4]; aP[0][mi][3] = Xs[ab + 8*260 + 4];
            }
            int w0 = tg*72, w1 = (tg + 4)*72;
            #pragma unroll
            for (int nf = 0; nf < 4; nf++) {
                int col = wn*32 + nf*8 + g;
                bP[0][nf][0] = Ws[w0 + col]; bP[0][nf][1] = Ws[w1 + col];
            }
        }
        #pragma unroll
        for (int s = 0; s < 32; s++) {
            int c = s & 1, nx = c ^ 1;
            if (s < 31) {
                #pragma unroll
                for (int mi = 0; mi < 2; mi++) {
                    int ab = (rbase + 16*mi)*260 + 8*(s+1) + tg;
                    aP[nx][mi][0] = Xs[ab];     aP[nx][mi][1] = Xs[ab + 8*260];
                    aP[nx][mi][2] = Xs[ab + 4]; aP[nx][mi][3] = Xs[ab + 8*260 + 4];
                }
                int w0 = (8*(s+1) + tg)*72, w1 = (8*(s+1) + tg + 4)*72;
                #pragma unroll
                for (int nf = 0; nf < 4; nf++) {
                    int col = wn*32 + nf*8 + g;
                    bP[nx][nf][0] = Ws[w0 + col]; bP[nx][nf][1] = Ws[w1 + col];
                }
            }
            #pragma unroll
            for (int mi = 0; mi < 2; mi++)
                #pragma unroll
                for (int nf = 0; nf < 4; nf++)
                    mma_tf32(acc[mi][nf], aP[c][mi], bP[c][nf][0], bP[c][nf][1]);
        }

        const float* bias = (sel == 0) ? bq : (sel == 1) ? bk : bv;
        unsigned* dst = (sel == 0) ? g_q : (sel == 1) ? g_k : g_vq;
        #pragma unroll
        for (int mi = 0; mi < 2; mi++) {
            size_t rg0 = (size_t)(row0 + rbase + 16*mi), rg1 = rg0 + 8;
            #pragma unroll
            for (int nf = 0; nf < 4; nf++) {
                int mcol = nto*64 + wn*32 + nf*8 + 2*tg;
                float b0 = bias[mcol], b1 = bias[mcol + 1];
                uint2 o0, o1;
                o0.x = f2tf(acc[mi][nf][0] + b0); o0.y = f2tf(acc[mi][nf][1] + b1);
                o1.x = f2tf(acc[mi][nf][2] + b0); o1.y = f2tf(acc[mi][nf][3] + b1);
                *(uint2*)(dst + rg0*256 + mcol) = o0;
                *(uint2*)(dst + rg1*256 + mcol) = o1;
            }
        }
    }
}

// ---------------------------------------------------------------------------
// core: per (batch, head): scores + warp-local softmax + S@V. 128 thr, 4 CTAs/SM
// ---------------------------------------------------------------------------
#define C_Q 0
#define C_K (64*68)
#define C_V (2*64*68)
#define C_U32 (3*64*68)    // 52224 B

__global__ __launch_bounds__(128, 4) void core_kernel() {
    extern __shared__ unsigned sm[];
    int t = threadIdx.x;
    int w = t >> 5, lane = t & 31;
    int g = lane >> 2, tg = lane & 3;
    int b = blockIdx.x, h = blockIdx.y;
    size_t rbase = (size_t)b * 64;

    for (int idx = t; idx < 1024; idx += 128) {
        int s = idx >> 4, c4 = idx & 15;
        *(uint4*)(sm + C_Q + s*68 + 4*c4) = *(const uint4*)(g_q + (rbase + s)*256 + h*64 + 4*c4);
        *(uint4*)(sm + C_K + s*68 + 4*c4) = *(const uint4*)(g_k + (rbase + s)*256 + h*64 + 4*c4);
    }
    for (int idx = t; idx < 4096; idx += 128) {
        int s = idx >> 6, d = idx & 63;
        sm[C_V + d*68 + s] = g_vq[(rbase + s)*256 + h*64 + d];
    }
    __syncthreads();

    int rowA = w*16 + g;

    float sc[8][4];
    #pragma unroll
    for (int i = 0; i < 8; i++) { sc[i][0] = sc[i][1] = sc[i][2] = sc[i][3] = 0.f; }
    #pragma unroll
    for (int s8 = 0; s8 < 8; s8++) {
        unsigned a[4];
        int ab = C_Q + rowA*68 + 8*s8 + tg;
        a[0] = sm[ab]; a[1] = sm[ab + 8*68]; a[2] = sm[ab + 4]; a[3] = sm[ab + 8*68 + 4];
        #pragma unroll
        for (int nf = 0; nf < 8; nf++) {
            int bb = C_K + (nf*8 + g)*68 + 8*s8 + tg;
            mma_tf32(sc[nf], a, sm[bb], sm[bb + 4]);
        }
    }

    const float NI = -3.402823466e38f;
    int rA = rowA, rB = rowA + 8;
    float mA = NI, mB = NI;
    #pragma unroll
    for (int nf = 0; nf < 8; nf++) {
        int c0 = nf*8 + 2*tg, c1 = c0 + 1;
        sc[nf][0] = (c0 <= rA) ? sc[nf][0]*0.125f : NI;
        sc[nf][1] = (c1 <= rA) ? sc[nf][1]*0.125f : NI;
        sc[nf][2] = (c0 <= rB) ? sc[nf][2]*0.125f : NI;
        sc[nf][3] = (c1 <= rB) ? sc[nf][3]*0.125f : NI;
        mA = fmaxf(mA, fmaxf(sc[nf][0], sc[nf][1]));
        mB = fmaxf(mB, fmaxf(sc[nf][2], sc[nf][3]));
    }
    mA = fmaxf(mA, __shfl_xor_sync(0xffffffffu, mA, 1));
    mA = fmaxf(mA, __shfl_xor_sync(0xffffffffu, mA, 2));
    mB = fmaxf(mB, __shfl_xor_sync(0xffffffffu, mB, 1));
    mB = fmaxf(mB, __shfl_xor_sync(0xffffffffu, mB, 2));
    float sA = 0.f, sB = 0.f;
    #pragma unroll
    for (int nf = 0; nf < 8; nf++) {
        int c0 = nf*8 + 2*tg, c1 = c0 + 1;
        float e0 = (c0 <= rA) ? __expf(sc[nf][0] - mA) : 0.f;
        float e1 = (c1 <= rA) ? __expf(sc[nf][1] - mA) : 0.f;
        float e2 = (c0 <= rB) ? __expf(sc[nf][2] - mB) : 0.f;
        float e3 = (c1 <= rB) ? __expf(sc[nf][3] - mB) : 0.f;
        sA += e0 + e1; sB += e2 + e3;
        sc[nf][0] = e0; sc[nf][1] = e1; sc[nf][2] = e2; sc[nf][3] = e3;
    }
    sA += __shfl_xor_sync(0xffffffffu, sA, 1);
    sA += __shfl_xor_sync(0xffffffffu, sA, 2);
    sB += __shfl_xor_sync(0xffffffffu, sB, 1);
    sB += __shfl_xor_sync(0xffffffffu, sB, 2);
    float iA = 1.f / sA, iB = 1.f / sB;
    unsigned P[8][4];
    #pragma unroll
    for (int nf = 0; nf < 8; nf++) {
        P[nf][0] = f2tf(sc[nf][0] * iA);
        P[nf][1] = f2tf(sc[nf][1] * iA);
        P[nf][2] = f2tf(sc[nf][2] * iB);
        P[nf][3] = f2tf(sc[nf][3] * iB);
    }

    float ha[8][4];
    #pragma unroll
    for (int i = 0; i < 8; i++) { ha[i][0] = ha[i][1] = ha[i][2] = ha[i][3] = 0.f; }
    int srcLo = (lane & 28) | (tg >> 1);
    int srcHi = srcLo + 2;
    bool odd = (tg & 1);
    #pragma unroll
    for (int s8 = 0; s8 < 8; s8++) {
        unsigned q00 = __shfl_sync(0xffffffffu, P[s8][0], srcLo);
        unsigned q01 = __shfl_sync(0xffffffffu, P[s8][1], srcLo);
        unsigned q10 = __shfl_sync(0xffffffffu, P[s8][2], srcLo);
        unsigned q11 = __shfl_sync(0xffffffffu, P[s8][3], srcLo);
        unsigned r00 = __shfl_sync(0xffffffffu, P[s8][0], srcHi);
        unsigned r01 = __shfl_sync(0xffffffffu, P[s8][1], srcHi);
        unsigned r10 = __shfl_sync(0xffffffffu, P[s8][2], srcHi);
        unsigned r11 = __shfl_sync(0xffffffffu, P[s8][3], srcHi);
        unsigned a[4];
        a[0] = odd ? q01 : q00;
        a[1] = odd ? q11 : q10;
        a[2] = odd ? r01 : r00;
        a[3] = odd ? r11 : r10;
        #pragma unroll
        for (int nf = 0; nf < 8; nf++) {
            int bb = C_V + (nf*8 + g)*68 + 8*s8 + tg;
            mma_tf32(ha[nf], a, sm[bb], sm[bb + 4]);
        }
    }

    #pragma unroll
    for (int nf = 0; nf < 8; nf++) {
        int gcol = h*64 + nf*8 + 2*tg;
        uint2 o0, o1;
        o0.x = f2tf(ha[nf][0]); o0.y = f2tf(ha[nf][1]);
        o1.x = f2tf(ha[nf][2]); o1.y = f2tf(ha[nf][3]);
        *(uint2*)(g_h + (rbase + rowA)*256 + gcol) = o0;
        *(uint2*)(g_h + (rbase + rowA + 8)*256 + gcol) = o1;
    }
}

// ---------------------------------------------------------------------------
// kout: [65536 x 256] x Wo + bo + residual; 256 thr, M2xN4 per warp
// ---------------------------------------------------------------------------
__global__ __launch_bounds__(256, 1) void kout_kernel(const float* __restrict__ bo) {
    extern __shared__ unsigned sm[];
    unsigned* Xs = sm;
    unsigned* Ws = sm + QK_WS;
    int t = threadIdx.x;
    int w = t >> 5, lane = t & 31;
    int g = lane >> 2, tg = lane & 3;
    int wm = w & 3, wn = w >> 2;
    int row0 = blockIdx.x * 128;

    {
        const uint4* xs = (const uint4*)(g_h + (size_t)row0*256);
        for (int idx = t; idx < 8192; idx += 256) {
            int r = idx >> 6, c4 = idx & 63;
            *(uint4*)(Xs + r*260 + 4*c4) = xs[idx];
        }
    }

    int rbase = wm*32 + g;

    for (int nt = 0; nt < 4; nt++) {
        __syncthreads();
        {
            const unsigned* wsrc = g_wt + 3*65536 + nt*64;
            for (int idx = t; idx < 4096; idx += 256) {
                int k = idx >> 4, c4 = idx & 15;
                *(uint4*)(Ws + k*72 + 4*c4) = *(const uint4*)(wsrc + k*256 + 4*c4);
            }
        }
        __syncthreads();

        float acc[2][4][4];
        #pragma unroll
        for (int mi = 0; mi < 2; mi++)
            #pragma unroll
            for (int nf = 0; nf < 4; nf++)
                #pragma unroll
                for (int j = 0; j < 4; j++) acc[mi][nf][j] = 0.f;

        unsigned aP[2][2][4], bP[2][4][2];
        {
            #pragma unroll
            for (int mi = 0; mi < 2; mi++) {
                int ab = (rbase + 16*mi)*260 + tg;
                aP[0][mi][0] = Xs[ab];     aP[0][mi][1] = Xs[ab + 8*260];
                aP[0][mi][2] = Xs[ab + 4]; aP[0][mi][3] = Xs[ab + 8*260 + 4];
            }
            int w0 = tg*72, w1 = (tg + 4)*72;
            #pragma unroll
            for (int nf = 0; nf < 4; nf++) {
                int col = wn*32 + nf*8 + g;
                bP[0][nf][0] = Ws[w0 + col]; bP[0][nf][1] = Ws[w1 + col];
            }
        }
        #pragma unroll
        for (int s = 0; s < 32; s++) {
            int c = s & 1, nx = c ^ 1;
            if (s < 31) {
                #pragma unroll
                for (int mi = 0; mi < 2; mi++) {
                    int ab = (rbase + 16*mi)*260 + 8*(s+1) + tg;
                    aP[nx][mi][0] = Xs[ab];     aP[nx][mi][1] = Xs[ab + 8*260];
                    aP[nx][mi][2] = Xs[ab + 4]; aP[nx][mi][3] = Xs[ab + 8*260 + 4];
                }
                int w0 = (8*(s+1) + tg)*72, w1 = (8*(s+1) + tg + 4)*72;
                #pragma unroll
                for (int nf = 0; nf < 4; nf++) {
                    int col = wn*32 + nf*8 + g;
                    bP[nx][nf][0] = Ws[w0 + col]; bP[nx][nf][1] = Ws[w1 + col];
                }
            }
            #pragma unroll
            for (int mi = 0; mi < 2; mi++)
                #pragma unroll
                for (int nf = 0; nf < 4; nf++)
                    mma_tf32(acc[mi][nf], aP[c][mi], bP[c][nf][0], bP[c][nf][1]);
        }

        #pragma unroll
        for (int mi = 0; mi < 2; mi++) {
            size_t rg0 = (size_t)(row0 + rbase + 16*mi), rg1 = rg0 + 8;
            #pragma unroll
            for (int nf = 0; nf < 4; nf++) {
                int mcol = nt*64 + wn*32 + nf*8 + 2*tg;
                float b0 = bo[mcol], b1 = bo[mcol + 1];
                float2 x0 = *(const float2*)(g_xt + rg0*256 + mcol);
                float2 x1 = *(const float2*)(g_xt + rg1*256 + mcol);
                *(float2*)(g_xattn + rg0*256 + mcol) =
                    make_float2(acc[mi][nf][0] + b0 + x0.x, acc[mi][nf][1] + b1 + x0.y);
                *(float2*)(g_xattn + rg1*256 + mcol) =
                    make_float2(acc[mi][nf][2] + b0 + x1.x, acc[mi][nf][3] + b1 + x1.y);
            }
        }
    }
}

// ---------------------------------------------------------------------------
// Kernel 1: normalize prototypes
// ---------------------------------------------------------------------------
__global__ void protonorm_kernel(const float* __restrict__ prot) {
    int r = blockIdx.x;
    int t = threadIdx.x;
    float v = prot[r*256 + t];
    float sq = v * v;
    #pragma unroll
    for (int off = 16; off > 0; off >>= 1)
        sq += __shfl_down_sync(0xffffffffu, sq, off);
    __shared__ float red[8];
    if ((t & 31) == 0) red[t >> 5] = sq;
    __syncthreads();
    __shared__ float rn;
    if (t == 0) {
        float sum = 0.f;
        #pragma unroll
        for (int i = 0; i < 8; i++) sum += red[i];
        rn = rsqrtf(sum);
    }
    __syncthreads();
    g_protn[r*256 + t] = v * rn;
}

// ---------------------------------------------------------------------------
// Kernel 2: instance-norm + dot + argmax -> hard idx
// ---------------------------------------------------------------------------
__global__ __launch_bounds__(256) void assign_kernel() {
    int p = blockIdx.x, n = blockIdx.y;
    extern __shared__ float smf[];
    float* Xs = smf;
    float* P  = Xs + 16384;
    float* MU = P + 1024;
    float* RS = MU + 256;
    int t = threadIdx.x;
    const float* src = g_xt + (size_t)(n*16 + p) * 16384;
    for (int i = t; i < 16384; i += 256) Xs[i] = src[i];
    const float* psrc = g_protn + p*1024;
    for (int i = t; i < 1024; i += 256) P[i] = psrc[i];
    __syncthreads();

    {
        float s1 = 0.f, s2 = 0.f;
        #pragma unroll
        for (int s = 0; s < 64; s++) {
            float v = Xs[s*256 + t];
            s1 += v; s2 += v*v;
        }
        float mu = s1 * 0.015625f;
        float var = s2 * 0.015625f - mu*mu;
        MU[t] = mu;
        RS[t] = rsqrtf(var + 1e-5f);
    }
    __syncthreads();

    int w = t >> 5, lane = t & 31;
    #pragma unroll
    for (int it = 0; it < 8; it++) {
        int s = w*8 + it;
        float d0 = 0.f, d1 = 0.f, d2 = 0.f, d3 = 0.f;
        #pragma unroll
        for (int cc = 0; cc < 8; cc++) {
            int c = lane + 32*cc;
            float y = (Xs[s*256 + c] - MU[c]) * RS[c];
            d0 = fmaf(y, P[c],       d0);
            d1 = fmaf(y, P[256 + c], d1);
            d2 = fmaf(y, P[512 + c], d2);
            d3 = fmaf(y, P[768 + c], d3);
        }
        #pragma unroll
        for (int off = 16; off > 0; off >>= 1) {
            d0 += __shfl_down_sync(0xffffffffu, d0, off);
            d1 += __shfl_down_sync(0xffffffffu, d1, off);
            d2 += __shfl_down_sync(0xffffffffu, d2, off);
            d3 += __shfl_down_sync(0xffffffffu, d3, off);
        }
        if (lane == 0) {
            int best = 0; float bv = d0;
            if (d1 > bv) { bv = d1; best = 1; }
            if (d2 > bv) { bv = d2; best = 2; }
            if (d3 > bv) { bv = d3; best = 3; }
            g_idx[(p*64 + n)*64 + s] = (unsigned char)best;
        }
    }
}

// ---------------------------------------------------------------------------
// Kernel 3: mode over parts -> cluster_indices (as float)
// ---------------------------------------------------------------------------
__global__ void mode_kernel(float* __restrict__ outci) {
    int id = blockIdx.x*256 + threadIdx.x;
    if (id >= NN*SS) return;
    int n = id >> 6, s = id & 63;
    int c0 = 0, c1 = 0, c2 = 0, c3 = 0;
    #pragma unroll
    for (int p = 0; p < 16; p++) {
        int a = g_idx[(p*64 + n)*64 + s];
        c0 += (a == 0); c1 += (a == 1); c2 += (a == 2); c3 += (a == 3);
    }
    int best = 0, bc = c0;
    if (c1 > bc) { bc = c1; best = 1; }
    if (c2 > bc) { bc = c2; best = 2; }
    if (c3 > bc) { bc = c3; best = 3; }
    outci[id] = (float)best;
}

// ---------------------------------------------------------------------------
// Kernel 5: scatter-max pooling
// ---------------------------------------------------------------------------
__global__ __launch_bounds__(256) void scatter_kernel() {
    int p = blockIdx.x, n = blockIdx.y, t = threadIdx.x;
    __shared__ unsigned char ids[64];
    if (t < 64) ids[t] = g_idx[(p*64 + n)*64 + t];
    __syncthreads();
    int c0 = 0, c1 = 0, c2 = 0, c3 = 0;
    #pragma unroll 8
    for (int s = 0; s < 64; s++) {
        int a = ids[s];
        c0 += (a == 0); c1 += (a == 1); c2 += (a == 2); c3 += (a == 3);
    }
    const float* src = g_xattn + (size_t)(n*16 + p)*16384 + t;
    float m0 = -3.402823466e38f, m1 = m0, m2 = m0, m3 = m0;
    #pragma unroll 8
    for (int s = 0; s < 64; s++) {
        float v = src[s*256];
        int a = ids[s];
        if (a == 0) m0 = fmaxf(m0, v);
        else if (a == 1) m1 = fmaxf(m1, v);
        else if (a == 2) m2 = fmaxf(m2, v);
        else m3 = fmaxf(m3, v);
    }
    if (c0 < 64) m0 = fmaxf(m0, 0.f);
    if (c1 < 64) m1 = fmaxf(m1, 0.f);
    if (c2 < 64) m2 = fmaxf(m2, 0.f);
    if (c3 < 64) m3 = fmaxf(m3, 0.f);
    float* dst = g_clustered + (size_t)(p*64 + n)*1024 + t;
    dst[0]   = m0;
    dst[256] = m1;
    dst[512] = m2;
    dst[768] = m3;
}

// ---------------------------------------------------------------------------
// Kernel 6: per-part FC
// ---------------------------------------------------------------------------
__global__ __launch_bounds__(256) void fc_kernel(const float* __restrict__ fcb,
                                                 float* __restrict__ out) {
    int p = blockIdx.x, n0 = blockIdx.y * 16, t = threadIdx.x;
    extern __shared__ float cl[];
    for (int nn = 0; nn < 16; nn++) {
        const float* src = g_clustered + (size_t)(p*64 + n0 + nn)*1024;
        for (int i = t; i < 1024; i += 256) cl[nn*1024 + i] = src[i];
    }
    __syncthreads();
    int o0 = t & 63, g = t >> 6;
    float acc[4][4];
    #pragma unroll
    for (int a = 0; a < 4; a++)
        #pragma unroll
        for (int bb = 0; bb < 4; bb++) acc[a][bb] = 0.f;
    const float* F = fcb + (size_t)p*1024*256 + o0;
    for (int kc = 0; kc < 1024; kc++) {
        float wv[4], cv[4];
        #pragma unroll
        for (int bb = 0; bb < 4; bb++) wv[bb] = F[(size_t)kc*256 + 64*bb];
        #pragma unroll
        for (int a = 0; a < 4; a++) cv[a] = cl[(g*4 + a)*1024 + kc];
        #pragma unroll
        for (int a = 0; a < 4; a++)
            #pragma unroll
            for (int bb = 0; bb < 4; bb++)
                acc[a][bb] = fmaf(cv[a], wv[bb], acc[a][bb]);
    }
    #pragma unroll
    for (int a = 0; a < 4; a++) {
        int n = n0 + g*4 + a;
        #pragma unroll
        for (int bb = 0; bb < 4; bb++) {
            int o = o0 + 64*bb;
            out[(size_t)n*4096 + o*16 + p] = acc[a][bb];
        }
    }
}

// ---------------------------------------------------------------------------
extern "C" void kernel_launch(void* const* d_in, const int* in_sizes, int n_in,
                              void* d_out, int out_size) {
    const float* x    = (const float*)d_in[0];
    const float* prot = (const float*)d_in[1];
    const float* Wq   = (const float*)d_in[2];
    const float* bq   = (const float*)d_in[3];
    const float* Wk   = (const float*)d_in[4];
    const float* bk   = (const float*)d_in[5];
    const float* Wv   = (const float*)d_in[6];
    const float* bv   = (const float*)d_in[7];
    const float* Wo   = (const float*)d_in[8];
    const float* bo   = (const float*)d_in[9];
    const float* fcb  = (const float*)d_in[10];
    float* out = (float*)d_out;

    cudaFuncSetAttribute(qkv_kernel,  cudaFuncAttributeMaxDynamicSharedMemorySize, QK_U32*4);
    cudaFuncSetAttribute(kout_kernel, cudaFuncAttributeMaxDynamicSharedMemorySize, QK_U32*4);
    cudaFuncSetAttribute(core_kernel, cudaFuncAttributeMaxDynamicSharedMemorySize, C_U32*4);
    cudaFuncSetAttribute(assign_kernel, cudaFuncAttributeMaxDynamicSharedMemorySize, 71680);
    cudaFuncSetAttribute(fc_kernel, cudaFuncAttributeMaxDynamicSharedMemorySize, 65536);

    transpose_kernel<<<NN*SS, 256>>>(x);
    packw_kernel<<<dim3(256, 4), 256>>>(Wq, Wk, Wv, Wo);
    qkv_kernel<<<512, 256, QK_U32*4>>>(bq, bk, bv);
    core_kernel<<<dim3(NB, 4), 128, C_U32*4>>>();
    kout_kernel<<<512, 256, QK_U32*4>>>(bo);
    protonorm_kernel<<<PP*KK, 256>>>(prot);
    assign_kernel<<<dim3(PP, NN), 256, 71680>>>();
    if (out_size >= NN*CC*PP + NN*SS)
        mode_kernel<<<16, 256>>>(out + NN*CC*PP);
    scatter_kernel<<<dim3(PP, NN), 256>>>();
    fc_kernel<<<dim3(PP, 4), 256, 65536>>>(fcb, out);
}